// round 8
// baseline (speedup 1.0000x reference)
#include <cuda_runtime.h>
#include <cuda_bf16.h>
#include <math.h>
#include <stdint.h>

#define H 128
#define N_IP_MAX 50000
#define N_CON_MAX 200000
#define MAXB 256

// ---------------- scratch ----------------
__device__ float g_tmpC[N_CON_MAX * H];
__device__ float g_ipA[N_IP_MAX * H];
__device__ float g_ipB[N_IP_MAX * H];
__device__ float g_conA[N_CON_MAX * H];
__device__ float g_conB[N_CON_MAX * H];
__device__ uint2 g_wsplit[10 * 16384];
__device__ int g_cnt[700032];      // .bss zero; fill counts it back down to zero
__device__ int g_off[700064];
__device__ int g_eidx[1800064];
__device__ int g_part[5 * MAXB];

struct EdgeDesc { const int* src; const int* dst; int nE; int n_dst; int dstbase; int ebase; };
struct BuildParams { EdgeDesc e[5]; };
struct CombSeg {
    const float* x;      // gather source (src-node features)
    const int* off;      // CSR offsets for dst rows
    const int* eidx;     // CSR source indices
    const float* xdst;   // dst (root) features
    const uint2* w; const float* bb;
    const float* addin; float* out; int n; int nblk; int mode;  // 0 norm,1 +lrelu,2 +addin+lrelu
};

// ---------------- helpers ----------------
__device__ __forceinline__ uint2 split2(float x0, float x1)
{
    uint32_t hi;
    asm("cvt.rn.bf16x2.f32 %0, %1, %2;" : "=r"(hi) : "f"(x1), "f"(x0));
    float h0 = __uint_as_float(hi << 16);
    float h1 = __uint_as_float(hi & 0xffff0000u);
    uint32_t lo;
    asm("cvt.rn.bf16x2.f32 %0, %1, %2;" : "=r"(lo) : "f"(x1 - h1), "f"(x0 - h0));
    return make_uint2(hi, lo);
}

__device__ __forceinline__ void mma16816(float* d, const uint32_t* a, uint32_t b0, uint32_t b1)
{
    asm volatile(
        "mma.sync.aligned.m16n8k16.row.col.f32.bf16.bf16.f32 "
        "{%0,%1,%2,%3}, {%4,%5,%6,%7}, {%8,%9}, {%0,%1,%2,%3};"
        : "+f"(d[0]), "+f"(d[1]), "+f"(d[2]), "+f"(d[3])
        : "r"(a[0]), "r"(a[1]), "r"(a[2]), "r"(a[3]), "r"(b0), "r"(b1));
}

__device__ __forceinline__ void cp_async16(uint32_t smem_dst, const void* gsrc)
{
    asm volatile("cp.async.ca.shared.global [%0], [%1], 16;" :: "r"(smem_dst), "l"(gsrc));
}
__device__ __forceinline__ void cp_commit() { asm volatile("cp.async.commit_group;"); }
__device__ __forceinline__ void cp_wait0()  { asm volatile("cp.async.wait_group 0;" ::: "memory"); }

// ---------------- fused presplit + degree count ----------------
__global__ void precount_kernel(const float* __restrict__ Wl_t, const float* __restrict__ Wr_t,
                                const float* __restrict__ Wl_s, const float* __restrict__ Wr_s,
                                uint2* __restrict__ out, BuildParams bp,
                                int* __restrict__ cnt, int cntBlocks)
{
    int bx = blockIdx.x;
    if (bx < 640) {
        int sg  = bx >> 6;
        int idx = (bx & 63) * 256 + threadIdx.x;
        int p = idx >> 7;
        int col = idx & 127;
        const float *Wl, *Wr;
        if (sg < 6) { Wl = Wl_t + (size_t)sg * H * H;       Wr = Wr_t + (size_t)sg * H * H; }
        else        { Wl = Wl_s + (size_t)(sg - 6) * H * H; Wr = Wr_s + (size_t)(sg - 6) * H * H; }
        int k0 = 2 * p;
        float x0 = (k0 < H)     ? Wl[k0 * H + col]       : Wr[(k0 - H) * H + col];
        float x1 = (k0 + 1 < H) ? Wl[(k0 + 1) * H + col] : Wr[(k0 + 1 - H) * H + col];
        out[(size_t)sg * 16384 + idx] = split2(x0, x1);
    } else {
        int b2 = bx - 640;
        int t = b2 / cntBlocks;
        int i = (b2 % cntBlocks) * 256 + threadIdx.x;
        EdgeDesc d = bp.e[t];
        if (i < d.nE) atomicAdd(&cnt[d.dstbase + d.dst[i]], 1);
    }
}

// ---------------- CSR scans ----------------
__global__ void scan_phase1(BuildParams bp, const int* __restrict__ cnt,
                            int* __restrict__ off, int* __restrict__ part)
{
    int t = blockIdx.y;
    EdgeDesc d = bp.e[t];
    int L = d.n_dst;
    int i = blockIdx.x * 1024 + threadIdx.x;
    __shared__ int sh[1024];
    int v = (i < L) ? cnt[d.dstbase + i] : 0;
    sh[threadIdx.x] = v;
    __syncthreads();
    for (int o = 1; o < 1024; o <<= 1) {
        int x = (threadIdx.x >= o) ? sh[threadIdx.x - o] : 0;
        __syncthreads();
        sh[threadIdx.x] += x;
        __syncthreads();
    }
    if (i < L) off[d.dstbase + t + i] = sh[threadIdx.x] - v;
    if (threadIdx.x == 1023) part[t * MAXB + blockIdx.x] = sh[1023];
}

__global__ void scan_phase23(BuildParams bp, int* __restrict__ off, const int* __restrict__ part)
{
    int t = blockIdx.y;
    EdgeDesc d = bp.e[t];
    int L = d.n_dst;
    __shared__ int pref[MAXB];
    if (threadIdx.x < MAXB) pref[threadIdx.x] = part[t * MAXB + threadIdx.x];
    __syncthreads();
    for (int o = 1; o < MAXB; o <<= 1) {
        int x = 0;
        if (threadIdx.x < MAXB && threadIdx.x >= o) x = pref[threadIdx.x - o];
        __syncthreads();
        if (threadIdx.x < MAXB) pref[threadIdx.x] += x;
        __syncthreads();
    }
    int add = (blockIdx.x == 0) ? 0 : pref[blockIdx.x - 1];
    int i = blockIdx.x * 1024 + threadIdx.x;
    if (i < L) off[d.dstbase + t + i] += add;
    if (blockIdx.x == 0 && threadIdx.x == 0) off[d.dstbase + t + L] = d.nE;
}

// fill: counts cnt back DOWN to zero (self-reinitializing across replays)
__global__ void fill_kernel(BuildParams bp, int* __restrict__ cnt,
                            const int* __restrict__ off, int* __restrict__ eidx)
{
    int t = blockIdx.y;
    EdgeDesc d = bp.e[t];
    int i = blockIdx.x * blockDim.x + threadIdx.x;
    if (i >= d.nE) return;
    int dd = d.dst[i];
    int pos = off[d.dstbase + t + dd] + atomicAdd(&cnt[d.dstbase + dd], -1) - 1;
    eidx[d.ebase + pos] = d.src[i];
}

// ---------------- fused SAGE combine: CSR gather + mma.sync + norm epilogue --------
#define ASTRIDE 16
#define WSTRIDE 264
#define DSMEM_BYTES ((2 * 256 * ASTRIDE + 128 * WSTRIDE) * 4)

__global__ void __launch_bounds__(512) combine_fused_kernel(CombSeg A, CombSeg B)
{
    extern __shared__ uint32_t dyn[];
    uint32_t* Asm0 = dyn;
    uint32_t* Asm1 = dyn + 256 * ASTRIDE;
    uint32_t* Wsm  = dyn + 2 * 256 * ASTRIDE;
    __shared__ float ssred[256];

    CombSeg cs;
    int blk = blockIdx.x;
    if (blk < A.nblk) cs = A;
    else { blk -= A.nblk; cs = B; }

    const int tid  = threadIdx.x;
    const int row0 = blk * 256;
    const int n    = cs.n;
    const int mode = cs.mode;

    // one-shot W stage
    {
        uint32_t wb = (uint32_t)__cvta_generic_to_shared(Wsm);
#pragma unroll
        for (int it = 0; it < 16; it++) {
            int ch = tid + it * 512;
            int p = ch >> 6, o = ch & 63;
            cp_async16(wb + (uint32_t)(p * WSTRIDE + o * 4) * 4, cs.w + p * 128 + o * 2);
        }
        cp_commit();
    }
    if (tid < 256) ssred[tid] = 0.0f;

    // ---- A producer mapping (CSR gather fused) ----
    const int ar   = tid >> 1;
    const int half = tid & 1;
    const int grow = row0 + ar;
    const bool rowok = grow < n;

    int e0 = 0, e1 = 0;
    float invdeg = 1.0f;
    if (rowok) {
        e0 = __ldg(cs.off + grow);
        e1 = __ldg(cs.off + grow + 1);
        invdeg = 1.0f / (float)max(e1 - e0, 1);
    }

    float af[8];
    auto load_a = [&](int kt) {
        int k0 = kt * 16 + half * 8;
        float4 f0 = make_float4(0.f, 0.f, 0.f, 0.f), f1 = f0;
        if (rowok) {
            if (k0 < H) {
                for (int e = e0; e < e1; e++) {
                    int si = __ldg(cs.eidx + e);
                    const float* p = cs.x + (size_t)si * H + k0;
                    float4 a = *reinterpret_cast<const float4*>(p);
                    float4 b = *reinterpret_cast<const float4*>(p + 4);
                    f0.x += a.x; f0.y += a.y; f0.z += a.z; f0.w += a.w;
                    f1.x += b.x; f1.y += b.y; f1.z += b.z; f1.w += b.w;
                }
                f0.x *= invdeg; f0.y *= invdeg; f0.z *= invdeg; f0.w *= invdeg;
                f1.x *= invdeg; f1.y *= invdeg; f1.z *= invdeg; f1.w *= invdeg;
            } else {
                const float* ap = cs.xdst + (size_t)grow * H + (k0 - H);
                f0 = *reinterpret_cast<const float4*>(ap);
                f1 = *reinterpret_cast<const float4*>(ap + 4);
            }
        }
        af[0] = f0.x; af[1] = f0.y; af[2] = f0.z; af[3] = f0.w;
        af[4] = f1.x; af[5] = f1.y; af[6] = f1.z; af[7] = f1.w;
    };

    auto store_a = [&](uint32_t* buf) {
#pragma unroll
        for (int j = 0; j < 4; j++) {
            int p = half * 4 + j;
            int q = (p < 4) ? (2 * p) : (2 * (p - 4) + 1);
            uint2 v = split2(af[2 * j], af[2 * j + 1]);
            *reinterpret_cast<uint2*>(&buf[ar * ASTRIDE + 2 * q]) = v;
        }
    };

    // ---- mma mapping ----
    const int lane = tid & 31;
    const int wid  = tid >> 5;
    const int wm   = wid >> 2;
    const int wn   = wid & 3;
    const int g    = lane >> 2;
    const int c    = lane & 3;

    float acc[4][4][4];
#pragma unroll
    for (int mt = 0; mt < 4; mt++)
#pragma unroll
        for (int nt = 0; nt < 4; nt++)
#pragma unroll
            for (int j = 0; j < 4; j++) acc[mt][nt][j] = 0.0f;

    load_a(0);
    store_a(Asm0);
    cp_wait0();
    __syncthreads();

    for (int kt = 0; kt < 16; kt++) {
        uint32_t* cur = (kt & 1) ? Asm1 : Asm0;
        uint32_t* nxt = (kt & 1) ? Asm0 : Asm1;
        if (kt < 15) load_a(kt + 1);

        uint32_t ahf[4][4], alf[4][4];
#pragma unroll
        for (int mt = 0; mt < 4; mt++) {
            int R = wm * 64 + mt * 16;
            uint4 v0 = *reinterpret_cast<const uint4*>(&cur[(R + g) * ASTRIDE + c * 4]);
            uint4 v1 = *reinterpret_cast<const uint4*>(&cur[(R + g + 8) * ASTRIDE + c * 4]);
            ahf[mt][0] = v0.x; ahf[mt][1] = v1.x; ahf[mt][2] = v0.z; ahf[mt][3] = v1.z;
            alf[mt][0] = v0.y; alf[mt][1] = v1.y; alf[mt][2] = v0.w; alf[mt][3] = v1.w;
        }
#pragma unroll
        for (int nt = 0; nt < 4; nt++) {
            int col = wn * 32 + nt * 8 + g;
            uint2 w0 = *reinterpret_cast<const uint2*>(&Wsm[(kt * 8 + c) * WSTRIDE + col * 2]);
            uint2 w1 = *reinterpret_cast<const uint2*>(&Wsm[(kt * 8 + c + 4) * WSTRIDE + col * 2]);
#pragma unroll
            for (int mt = 0; mt < 4; mt++) {
                mma16816(acc[mt][nt], ahf[mt], w0.x, w1.x);
                mma16816(acc[mt][nt], ahf[mt], w0.y, w1.y);
                mma16816(acc[mt][nt], alf[mt], w0.x, w1.x);
            }
        }

        if (kt < 15) store_a(nxt);
        __syncthreads();
    }

    // ---- epilogue ----
#pragma unroll
    for (int mt = 0; mt < 4; mt++) {
        float ss0 = 0.0f, ss1 = 0.0f;
#pragma unroll
        for (int nt = 0; nt < 4; nt++) {
            int col = wn * 32 + nt * 8 + c * 2;
            float b0v = __ldg(cs.bb + col), b1v = __ldg(cs.bb + col + 1);
            acc[mt][nt][0] += b0v; acc[mt][nt][1] += b1v;
            acc[mt][nt][2] += b0v; acc[mt][nt][3] += b1v;
            ss0 += acc[mt][nt][0] * acc[mt][nt][0] + acc[mt][nt][1] * acc[mt][nt][1];
            ss1 += acc[mt][nt][2] * acc[mt][nt][2] + acc[mt][nt][3] * acc[mt][nt][3];
        }
        ss0 += __shfl_xor_sync(0xffffffffu, ss0, 1);
        ss0 += __shfl_xor_sync(0xffffffffu, ss0, 2);
        ss1 += __shfl_xor_sync(0xffffffffu, ss1, 1);
        ss1 += __shfl_xor_sync(0xffffffffu, ss1, 2);
        if (c == 0) {
            atomicAdd(&ssred[wm * 64 + mt * 16 + g],     ss0);
            atomicAdd(&ssred[wm * 64 + mt * 16 + 8 + g], ss1);
        }
    }
    __syncthreads();

#pragma unroll
    for (int mt = 0; mt < 4; mt++) {
        int rl0 = wm * 64 + mt * 16 + g;
        int rl1 = rl0 + 8;
        float inv0 = 1.0f / fmaxf(sqrtf(ssred[rl0]), 1e-12f);
        float inv1 = 1.0f / fmaxf(sqrtf(ssred[rl1]), 1e-12f);
        int gr0 = row0 + rl0;
        int gr1 = row0 + rl1;
#pragma unroll
        for (int nt = 0; nt < 4; nt++) {
            int col = wn * 32 + nt * 8 + c * 2;
            if (gr0 < n) {
                float v0 = acc[mt][nt][0] * inv0;
                float v1 = acc[mt][nt][1] * inv0;
                if (mode == 2) {
                    float2 a2 = *reinterpret_cast<const float2*>(cs.addin + (size_t)gr0 * H + col);
                    v0 += a2.x; v1 += a2.y;
                }
                if (mode >= 1) {
                    v0 = (v0 >= 0.f) ? v0 : 0.01f * v0;
                    v1 = (v1 >= 0.f) ? v1 : 0.01f * v1;
                }
                *reinterpret_cast<float2*>(cs.out + (size_t)gr0 * H + col) = make_float2(v0, v1);
            }
            if (gr1 < n) {
                float v2 = acc[mt][nt][2] * inv1;
                float v3 = acc[mt][nt][3] * inv1;
                if (mode == 2) {
                    float2 a2 = *reinterpret_cast<const float2*>(cs.addin + (size_t)gr1 * H + col);
                    v2 += a2.x; v3 += a2.y;
                }
                if (mode >= 1) {
                    v2 = (v2 >= 0.f) ? v2 : 0.01f * v2;
                    v3 = (v3 >= 0.f) ? v3 : 0.01f * v3;
                }
                *reinterpret_cast<float2*>(cs.out + (size_t)gr1 * H + col) = make_float2(v2, v3);
            }
        }
    }
}

// ---------------- host ----------------
extern "C" void kernel_launch(void* const* d_in, const int* in_sizes, int n_in,
                              void* d_out, int out_size)
{
    const float* x_ip  = (const float*)d_in[0];
    const float* x_con = (const float*)d_in[1];
    const int* src_ipcon = (const int*)d_in[2];
    const int* dst_ipcon = (const int*)d_in[3];
    const int* src_conip = (const int*)d_in[4];
    const int* dst_conip = (const int*)d_in[5];
    const int* src_ipip  = (const int*)d_in[6];
    const int* dst_ipip  = (const int*)d_in[7];
    const int* src_csrc  = (const int*)d_in[8];
    const int* dst_csrc  = (const int*)d_in[9];
    const int* src_cdst  = (const int*)d_in[10];
    const int* dst_cdst  = (const int*)d_in[11];
    const float* Wl_t = (const float*)d_in[12];
    const float* bl_t = (const float*)d_in[13];
    const float* Wr_t = (const float*)d_in[14];
    const float* Wl_s = (const float*)d_in[15];
    const float* bl_s = (const float*)d_in[16];
    const float* Wr_s = (const float*)d_in[17];

    const int n_ip  = in_sizes[0] / H;
    const int n_con = in_sizes[1] / H;
    const int nE_ipcon = in_sizes[2];
    const int nE_conip = in_sizes[4];
    const int nE_ipip  = in_sizes[6];
    const int nE_csrc  = in_sizes[8];
    const int nE_cdst  = in_sizes[10];

    float *tmpC, *ipA, *ipB, *conA, *conB;
    uint2* wsp;
    int *cnt, *off, *eidx, *part;
    cudaGetSymbolAddress((void**)&tmpC, g_tmpC);
    cudaGetSymbolAddress((void**)&ipA,  g_ipA);
    cudaGetSymbolAddress((void**)&ipB,  g_ipB);
    cudaGetSymbolAddress((void**)&conA, g_conA);
    cudaGetSymbolAddress((void**)&conB, g_conB);
    cudaGetSymbolAddress((void**)&wsp,  g_wsplit);
    cudaGetSymbolAddress((void**)&cnt,  g_cnt);
    cudaGetSymbolAddress((void**)&off,  g_off);
    cudaGetSymbolAddress((void**)&eidx, g_eidx);
    cudaGetSymbolAddress((void**)&part, g_part);

    cudaFuncSetAttribute(combine_fused_kernel, cudaFuncAttributeMaxDynamicSharedMemorySize, DSMEM_BYTES);

    float* out = (float*)d_out;

    BuildParams bp;
    bp.e[0] = { src_ipip,  dst_ipip,  nE_ipip,  n_ip,  0,                0 };
    bp.e[1] = { src_csrc,  dst_csrc,  nE_csrc,  n_con, n_ip,             nE_ipip };
    bp.e[2] = { src_cdst,  dst_cdst,  nE_cdst,  n_con, n_ip + n_con,     nE_ipip + nE_csrc };
    bp.e[3] = { src_ipcon, dst_ipcon, nE_ipcon, n_con, n_ip + 2 * n_con, nE_ipip + nE_csrc + nE_cdst };
    bp.e[4] = { src_conip, dst_conip, nE_conip, n_ip,  n_ip + 3 * n_con, nE_ipip + nE_csrc + nE_cdst + nE_ipcon };

    int maxE = nE_ipip;
    if (nE_csrc  > maxE) maxE = nE_csrc;
    if (nE_cdst  > maxE) maxE = nE_cdst;
    if (nE_ipcon > maxE) maxE = nE_ipcon;
    if (nE_conip > maxE) maxE = nE_conip;
    const int cntBlocks = (maxE + 255) / 256;

    precount_kernel<<<640 + 5 * cntBlocks, 256>>>(Wl_t, Wr_t, Wl_s, Wr_s, wsp, bp, cnt, cntBlocks);
    scan_phase1<<<dim3(MAXB, 5), 1024>>>(bp, cnt, off, part);
    scan_phase23<<<dim3(MAXB, 5), 1024>>>(bp, off, part);
    fill_kernel<<<dim3(cntBlocks, 5), 256>>>(bp, cnt, off, eidx);

    const int* off0 = off + bp.e[0].dstbase + 0;
    const int* off1 = off + bp.e[1].dstbase + 1;
    const int* off2 = off + bp.e[2].dstbase + 2;
    const int* off3 = off + bp.e[3].dstbase + 3;
    const int* off4 = off + bp.e[4].dstbase + 4;
    const int* ei0 = eidx + bp.e[0].ebase;
    const int* ei1 = eidx + bp.e[1].ebase;
    const int* ei2 = eidx + bp.e[2].ebase;
    const int* ei3 = eidx + bp.e[3].ebase;
    const int* ei4 = eidx + bp.e[4].ebase;

    const int nbIP  = (n_ip  + 255) / 256;
    const int nbCON = (n_con + 255) / 256;
    const size_t WSZ = 16384;

    for (int l = 0; l < 2; l++) {
        const float* xi = (l == 0) ? x_ip  : ipB;
        const float* xc = (l == 0) ? x_con : conB;

        const float* b0 = bl_t + (size_t)(l * 3 + 0) * H;
        const float* b1 = bl_t + (size_t)(l * 3 + 1) * H;
        const float* b2 = bl_t + (size_t)(l * 3 + 2) * H;
        const float* bs0 = bl_s + (size_t)(l * 2 + 0) * H;
        const float* bs1 = bl_s + (size_t)(l * 2 + 1) * H;

        // ---------- temporal: (ip sage + con sage1) fused, then con sage2 ----------
        CombSeg cIP = { xi, off0, ei0, xi, wsp + (size_t)(l * 3 + 0) * WSZ, b0, nullptr, ipA,  n_ip,  nbIP,  1 };
        CombSeg cC1 = { xc, off1, ei1, xc, wsp + (size_t)(l * 3 + 1) * WSZ, b1, nullptr, tmpC, n_con, nbCON, 0 };
        combine_fused_kernel<<<nbIP + nbCON, 512, DSMEM_BYTES>>>(cIP, cC1);

        CombSeg cC2 = { xc, off2, ei2, xc, wsp + (size_t)(l * 3 + 2) * WSZ, b2, tmpC, conA, n_con, nbCON, 2 };
        CombSeg cNil = {};
        combine_fused_kernel<<<nbCON, 512, DSMEM_BYTES>>>(cC2, cNil);

        // ---------- spatial combines fused (gather directly from ipA/conA) ----------
        float* out_ip  = (l == 1) ? out : ipB;
        float* out_con = (l == 1) ? (out + (size_t)n_ip * H) : conB;

        CombSeg cSC = { ipA,  off3, ei3, conA, wsp + (size_t)(6 + l * 2 + 0) * WSZ, bs0, nullptr, out_con, n_con, nbCON, 1 };
        CombSeg cSI = { conA, off4, ei4, ipA,  wsp + (size_t)(6 + l * 2 + 1) * WSZ, bs1, nullptr, out_ip,  n_ip,  nbIP,  1 };
        combine_fused_kernel<<<nbCON + nbIP, 512, DSMEM_BYTES>>>(cSC, cSI);
    }
}

// round 9
// speedup vs baseline: 1.0019x; 1.0019x over previous
#include <cuda_runtime.h>
#include <cuda_bf16.h>
#include <math.h>
#include <stdint.h>

#define H 128
#define N_IP_MAX 50000
#define N_CON_MAX 200000
#define MAXB 256

// ---------------- scratch ----------------
// s buffers hold agg output in SPLIT format: [row][8 ksteps][16 u32] (512B/row)
__device__ uint32_t g_s0[N_IP_MAX * 128];
__device__ uint32_t g_s1[N_CON_MAX * 128];
__device__ uint32_t g_s2[N_CON_MAX * 128];
__device__ float g_tmpC[N_CON_MAX * H];
__device__ float g_ipA[N_IP_MAX * H];
__device__ float g_ipB[N_IP_MAX * H];
__device__ float g_conA[N_CON_MAX * H];
__device__ float g_conB[N_CON_MAX * H];
__device__ uint2 g_wsplit[10 * 16384];
__device__ int g_cnt[700032];      // .bss zero; fill counts it back down to zero
__device__ int g_off[700064];
__device__ int g_eidx[1800064];
__device__ int g_part[5 * MAXB];

struct EdgeDesc { const int* src; const int* dst; int nE; int n_dst; int dstbase; int ebase; };
struct BuildParams { EdgeDesc e[5]; };
struct AggSeg { const float* x; const int* off; const int* eidx; uint32_t* s; int n; };
struct CombSeg {
    const uint32_t* s;   // split-format agg output
    const float* xdst;   // dst (root) features, fp32
    const uint2* w; const float* bb;
    const float* addin; float* out; int n; int nblk; int mode;  // 0 norm,1 +lrelu,2 +addin+lrelu
};

// ---------------- helpers ----------------
__device__ __forceinline__ uint2 split2(float x0, float x1)
{
    uint32_t hi;
    asm("cvt.rn.bf16x2.f32 %0, %1, %2;" : "=r"(hi) : "f"(x1), "f"(x0));
    float h0 = __uint_as_float(hi << 16);
    float h1 = __uint_as_float(hi & 0xffff0000u);
    uint32_t lo;
    asm("cvt.rn.bf16x2.f32 %0, %1, %2;" : "=r"(lo) : "f"(x1 - h1), "f"(x0 - h0));
    return make_uint2(hi, lo);
}

__device__ __forceinline__ void mma16816(float* d, const uint32_t* a, uint32_t b0, uint32_t b1)
{
    asm volatile(
        "mma.sync.aligned.m16n8k16.row.col.f32.bf16.bf16.f32 "
        "{%0,%1,%2,%3}, {%4,%5,%6,%7}, {%8,%9}, {%0,%1,%2,%3};"
        : "+f"(d[0]), "+f"(d[1]), "+f"(d[2]), "+f"(d[3])
        : "r"(a[0]), "r"(a[1]), "r"(a[2]), "r"(a[3]), "r"(b0), "r"(b1));
}

__device__ __forceinline__ void cp_async16(uint32_t smem_dst, const void* gsrc)
{
    asm volatile("cp.async.ca.shared.global [%0], [%1], 16;" :: "r"(smem_dst), "l"(gsrc));
}
__device__ __forceinline__ void cp_commit() { asm volatile("cp.async.commit_group;"); }
__device__ __forceinline__ void cp_wait0()  { asm volatile("cp.async.wait_group 0;" ::: "memory"); }

// slot permutation for pair p in [0,8): [0,4,1,5,2,6,3,7]
__device__ __forceinline__ int permq(int p) { return (p < 4) ? (2 * p) : (2 * (p - 4) + 1); }

// ---------------- fused presplit + degree count ----------------
__global__ void precount_kernel(const float* __restrict__ Wl_t, const float* __restrict__ Wr_t,
                                const float* __restrict__ Wl_s, const float* __restrict__ Wr_s,
                                uint2* __restrict__ out, BuildParams bp,
                                int* __restrict__ cnt, int cntBlocks)
{
    int bx = blockIdx.x;
    if (bx < 640) {
        int sg  = bx >> 6;
        int idx = (bx & 63) * 256 + threadIdx.x;
        int p = idx >> 7;
        int col = idx & 127;
        const float *Wl, *Wr;
        if (sg < 6) { Wl = Wl_t + (size_t)sg * H * H;       Wr = Wr_t + (size_t)sg * H * H; }
        else        { Wl = Wl_s + (size_t)(sg - 6) * H * H; Wr = Wr_s + (size_t)(sg - 6) * H * H; }
        int k0 = 2 * p;
        float x0 = (k0 < H)     ? Wl[k0 * H + col]       : Wr[(k0 - H) * H + col];
        float x1 = (k0 + 1 < H) ? Wl[(k0 + 1) * H + col] : Wr[(k0 + 1 - H) * H + col];
        out[(size_t)sg * 16384 + idx] = split2(x0, x1);
    } else {
        int b2 = bx - 640;
        int t = b2 / cntBlocks;
        int i = (b2 % cntBlocks) * 256 + threadIdx.x;
        EdgeDesc d = bp.e[t];
        if (i < d.nE) atomicAdd(&cnt[d.dstbase + d.dst[i]], 1);
    }
}

// ---------------- CSR scans ----------------
__global__ void scan_phase1(BuildParams bp, const int* __restrict__ cnt,
                            int* __restrict__ off, int* __restrict__ part)
{
    int t = blockIdx.y;
    EdgeDesc d = bp.e[t];
    int L = d.n_dst;
    int i = blockIdx.x * 1024 + threadIdx.x;
    __shared__ int sh[1024];
    int v = (i < L) ? cnt[d.dstbase + i] : 0;
    sh[threadIdx.x] = v;
    __syncthreads();
    for (int o = 1; o < 1024; o <<= 1) {
        int x = (threadIdx.x >= o) ? sh[threadIdx.x - o] : 0;
        __syncthreads();
        sh[threadIdx.x] += x;
        __syncthreads();
    }
    if (i < L) off[d.dstbase + t + i] = sh[threadIdx.x] - v;
    if (threadIdx.x == 1023) part[t * MAXB + blockIdx.x] = sh[1023];
}

__global__ void scan_phase23(BuildParams bp, int* __restrict__ off, const int* __restrict__ part)
{
    int t = blockIdx.y;
    EdgeDesc d = bp.e[t];
    int L = d.n_dst;
    __shared__ int pref[MAXB];
    if (threadIdx.x < MAXB) pref[threadIdx.x] = part[t * MAXB + threadIdx.x];
    __syncthreads();
    for (int o = 1; o < MAXB; o <<= 1) {
        int x = 0;
        if (threadIdx.x < MAXB && threadIdx.x >= o) x = pref[threadIdx.x - o];
        __syncthreads();
        if (threadIdx.x < MAXB) pref[threadIdx.x] += x;
        __syncthreads();
    }
    int add = (blockIdx.x == 0) ? 0 : pref[blockIdx.x - 1];
    int i = blockIdx.x * 1024 + threadIdx.x;
    if (i < L) off[d.dstbase + t + i] += add;
    if (blockIdx.x == 0 && threadIdx.x == 0) off[d.dstbase + t + L] = d.nE;
}

// fill: counts cnt back DOWN to zero (self-reinitializing across replays)
__global__ void fill_kernel(BuildParams bp, int* __restrict__ cnt,
                            const int* __restrict__ off, int* __restrict__ eidx)
{
    int t = blockIdx.y;
    EdgeDesc d = bp.e[t];
    int i = blockIdx.x * blockDim.x + threadIdx.x;
    if (i >= d.nE) return;
    int dd = d.dst[i];
    int pos = off[d.dstbase + t + dd] + atomicAdd(&cnt[d.dstbase + dd], -1) - 1;
    eidx[d.ebase + pos] = d.src[i];
}

// ---------------- fused CSR mean-aggregation, split-format output ----------------
// warp per dst row; lane covers k = 4*lane..4*lane+3 (pairs 2*lane, 2*lane+1)
__global__ void agg_fused_kernel(AggSeg a0, AggSeg a1, AggSeg a2)
{
    AggSeg sg;
    if (blockIdx.y == 0) sg = a0;
    else if (blockIdx.y == 1) sg = a1;
    else sg = a2;
    int w = (blockIdx.x * blockDim.x + threadIdx.x) >> 5;
    int lane = threadIdx.x & 31;
    if (w >= sg.n) return;
    int start = sg.off[w], end = sg.off[w + 1];
    float4 acc = make_float4(0.f, 0.f, 0.f, 0.f);
    int e = start;
    for (; e + 1 < end; e += 2) {
        int si0 = __ldg(sg.eidx + e);
        int si1 = __ldg(sg.eidx + e + 1);
        float4 v0 = reinterpret_cast<const float4*>(sg.x)[(size_t)si0 * 32 + lane];
        float4 v1 = reinterpret_cast<const float4*>(sg.x)[(size_t)si1 * 32 + lane];
        acc.x += v0.x + v1.x; acc.y += v0.y + v1.y;
        acc.z += v0.z + v1.z; acc.w += v0.w + v1.w;
    }
    if (e < end) {
        int si = __ldg(sg.eidx + e);
        float4 v = reinterpret_cast<const float4*>(sg.x)[(size_t)si * 32 + lane];
        acc.x += v.x; acc.y += v.y; acc.z += v.z; acc.w += v.w;
    }
    float inv = 1.0f / (float)max(end - start, 1);
    acc.x *= inv; acc.y *= inv; acc.z *= inv; acc.w *= inv;

    // split + permuted store
    int P0 = 2 * lane;                 // global k-pair
    int kt = P0 >> 3;                  // k-step 0..7
    int p0 = P0 & 7, p1 = p0 + 1;
    uint2 v0 = split2(acc.x, acc.y);
    uint2 v1 = split2(acc.z, acc.w);
    uint32_t* base = sg.s + (size_t)w * 128 + kt * 16;
    *reinterpret_cast<uint2*>(base + 2 * permq(p0)) = v0;
    *reinterpret_cast<uint2*>(base + 2 * permq(p1)) = v1;
}

// ---------------- fused SAGE combine (mma.sync, 3x-bf16 split, W fully staged) --------
#define ASTRIDE 16
#define WSTRIDE 264
#define DSMEM_BYTES ((2 * 256 * ASTRIDE + 128 * WSTRIDE) * 4)

__global__ void __launch_bounds__(512) combine_fused_kernel(CombSeg A, CombSeg B)
{
    extern __shared__ uint32_t dyn[];
    uint32_t* Asm0 = dyn;
    uint32_t* Asm1 = dyn + 256 * ASTRIDE;
    uint32_t* Wsm  = dyn + 2 * 256 * ASTRIDE;
    __shared__ float ssred[4][256];

    CombSeg cs;
    int blk = blockIdx.x;
    if (blk < A.nblk) cs = A;
    else { blk -= A.nblk; cs = B; }

    const int tid  = threadIdx.x;
    const int row0 = blk * 256;
    const int n    = cs.n;
    const int mode = cs.mode;

    // one-shot W stage
    {
        uint32_t wb = (uint32_t)__cvta_generic_to_shared(Wsm);
#pragma unroll
        for (int it = 0; it < 16; it++) {
            int ch = tid + it * 512;
            int p = ch >> 6, o = ch & 63;
            cp_async16(wb + (uint32_t)(p * WSTRIDE + o * 4) * 4, cs.w + p * 128 + o * 2);
        }
        cp_commit();
    }

    // ---- A producer mapping ----
    const int ar   = tid >> 1;
    const int half = tid & 1;
    const int grow = row0 + ar;
    const bool rowok = grow < n;

    float af[8];
    uint4 ru0, ru1;
    auto load_a = [&](int kt) {
        if (kt < 8) {
            // s-half: already split+permuted in global
            if (rowok) {
                const uint4* sp = reinterpret_cast<const uint4*>(
                    cs.s + (size_t)grow * 128 + kt * 16 + half * 8);
                ru0 = sp[0]; ru1 = sp[1];
            } else {
                ru0 = make_uint4(0, 0, 0, 0); ru1 = ru0;
            }
        } else {
            int k0 = (kt - 8) * 16 + half * 8;
            float4 f0 = make_float4(0.f, 0.f, 0.f, 0.f), f1 = f0;
            if (rowok) {
                const float* ap = cs.xdst + (size_t)grow * H + k0;
                f0 = *reinterpret_cast<const float4*>(ap);
                f1 = *reinterpret_cast<const float4*>(ap + 4);
            }
            af[0] = f0.x; af[1] = f0.y; af[2] = f0.z; af[3] = f0.w;
            af[4] = f1.x; af[5] = f1.y; af[6] = f1.z; af[7] = f1.w;
        }
    };

    auto store_a = [&](uint32_t* buf, int kt) {
        if (kt < 8) {
            uint4* dst = reinterpret_cast<uint4*>(&buf[ar * ASTRIDE + half * 8]);
            dst[0] = ru0; dst[1] = ru1;
        } else {
#pragma unroll
            for (int j = 0; j < 4; j++) {
                int p = half * 4 + j;
                int q = permq(p);
                uint2 v = split2(af[2 * j], af[2 * j + 1]);
                *reinterpret_cast<uint2*>(&buf[ar * ASTRIDE + 2 * q]) = v;
            }
        }
    };

    // ---- mma mapping ----
    const int lane = tid & 31;
    const int wid  = tid >> 5;
    const int wm   = wid >> 2;
    const int wn   = wid & 3;
    const int g    = lane >> 2;
    const int c    = lane & 3;

    float acc[4][4][4];
#pragma unroll
    for (int mt = 0; mt < 4; mt++)
#pragma unroll
        for (int nt = 0; nt < 4; nt++)
#pragma unroll
            for (int j = 0; j < 4; j++) acc[mt][nt][j] = 0.0f;

    load_a(0);
    store_a(Asm0, 0);
    cp_wait0();
    __syncthreads();

    for (int kt = 0; kt < 16; kt++) {
        uint32_t* cur = (kt & 1) ? Asm1 : Asm0;
        uint32_t* nxt = (kt & 1) ? Asm0 : Asm1;
        if (kt < 15) load_a(kt + 1);

        uint32_t ahf[4][4], alf[4][4];
#pragma unroll
        for (int mt = 0; mt < 4; mt++) {
            int R = wm * 64 + mt * 16;
            uint4 v0 = *reinterpret_cast<const uint4*>(&cur[(R + g) * ASTRIDE + c * 4]);
            uint4 v1 = *reinterpret_cast<const uint4*>(&cur[(R + g + 8) * ASTRIDE + c * 4]);
            ahf[mt][0] = v0.x; ahf[mt][1] = v1.x; ahf[mt][2] = v0.z; ahf[mt][3] = v1.z;
            alf[mt][0] = v0.y; alf[mt][1] = v1.y; alf[mt][2] = v0.w; alf[mt][3] = v1.w;
        }
#pragma unroll
        for (int nt = 0; nt < 4; nt++) {
            int col = wn * 32 + nt * 8 + g;
            uint2 w0 = *reinterpret_cast<const uint2*>(&Wsm[(kt * 8 + c) * WSTRIDE + col * 2]);
            uint2 w1 = *reinterpret_cast<const uint2*>(&Wsm[(kt * 8 + c + 4) * WSTRIDE + col * 2]);
#pragma unroll
            for (int mt = 0; mt < 4; mt++) {
                mma16816(acc[mt][nt], ahf[mt], w0.x, w1.x);
                mma16816(acc[mt][nt], ahf[mt], w0.y, w1.y);
                mma16816(acc[mt][nt], alf[mt], w0.x, w1.x);
            }
        }

        if (kt < 15) store_a(nxt, kt + 1);
        __syncthreads();
    }

    // ---- epilogue ----
#pragma unroll
    for (int mt = 0; mt < 4; mt++) {
        float ss0 = 0.0f, ss1 = 0.0f;
#pragma unroll
        for (int nt = 0; nt < 4; nt++) {
            int col = wn * 32 + nt * 8 + c * 2;
            float b0v = __ldg(cs.bb + col), b1v = __ldg(cs.bb + col + 1);
            acc[mt][nt][0] += b0v; acc[mt][nt][1] += b1v;
            acc[mt][nt][2] += b0v; acc[mt][nt][3] += b1v;
            ss0 += acc[mt][nt][0] * acc[mt][nt][0] + acc[mt][nt][1] * acc[mt][nt][1];
            ss1 += acc[mt][nt][2] * acc[mt][nt][2] + acc[mt][nt][3] * acc[mt][nt][3];
        }
        ss0 += __shfl_xor_sync(0xffffffffu, ss0, 1);
        ss0 += __shfl_xor_sync(0xffffffffu, ss0, 2);
        ss1 += __shfl_xor_sync(0xffffffffu, ss1, 1);
        ss1 += __shfl_xor_sync(0xffffffffu, ss1, 2);
        if (c == 0) {
            ssred[wn][wm * 64 + mt * 16 + g]     = ss0;
            ssred[wn][wm * 64 + mt * 16 + 8 + g] = ss1;
        }
    }
    __syncthreads();

#pragma unroll
    for (int mt = 0; mt < 4; mt++) {
        int rl0 = wm * 64 + mt * 16 + g;
        int rl1 = rl0 + 8;
        float t0 = ssred[0][rl0] + ssred[1][rl0] + ssred[2][rl0] + ssred[3][rl0];
        float t1 = ssred[0][rl1] + ssred[1][rl1] + ssred[2][rl1] + ssred[3][rl1];
        float inv0 = 1.0f / fmaxf(sqrtf(t0), 1e-12f);
        float inv1 = 1.0f / fmaxf(sqrtf(t1), 1e-12f);
        int gr0 = row0 + rl0;
        int gr1 = row0 + rl1;
#pragma unroll
        for (int nt = 0; nt < 4; nt++) {
            int col = wn * 32 + nt * 8 + c * 2;
            if (gr0 < n) {
                float v0 = acc[mt][nt][0] * inv0;
                float v1 = acc[mt][nt][1] * inv0;
                if (mode == 2) {
                    float2 a2 = *reinterpret_cast<const float2*>(cs.addin + (size_t)gr0 * H + col);
                    v0 += a2.x; v1 += a2.y;
                }
                if (mode >= 1) {
                    v0 = (v0 >= 0.f) ? v0 : 0.01f * v0;
                    v1 = (v1 >= 0.f) ? v1 : 0.01f * v1;
                }
                *reinterpret_cast<float2*>(cs.out + (size_t)gr0 * H + col) = make_float2(v0, v1);
            }
            if (gr1 < n) {
                float v2 = acc[mt][nt][2] * inv1;
                float v3 = acc[mt][nt][3] * inv1;
                if (mode == 2) {
                    float2 a2 = *reinterpret_cast<const float2*>(cs.addin + (size_t)gr1 * H + col);
                    v2 += a2.x; v3 += a2.y;
                }
                if (mode >= 1) {
                    v2 = (v2 >= 0.f) ? v2 : 0.01f * v2;
                    v3 = (v3 >= 0.f) ? v3 : 0.01f * v3;
                }
                *reinterpret_cast<float2*>(cs.out + (size_t)gr1 * H + col) = make_float2(v2, v3);
            }
        }
    }
}

// ---------------- host ----------------
extern "C" void kernel_launch(void* const* d_in, const int* in_sizes, int n_in,
                              void* d_out, int out_size)
{
    const float* x_ip  = (const float*)d_in[0];
    const float* x_con = (const float*)d_in[1];
    const int* src_ipcon = (const int*)d_in[2];
    const int* dst_ipcon = (const int*)d_in[3];
    const int* src_conip = (const int*)d_in[4];
    const int* dst_conip = (const int*)d_in[5];
    const int* src_ipip  = (const int*)d_in[6];
    const int* dst_ipip  = (const int*)d_in[7];
    const int* src_csrc  = (const int*)d_in[8];
    const int* dst_csrc  = (const int*)d_in[9];
    const int* src_cdst  = (const int*)d_in[10];
    const int* dst_cdst  = (const int*)d_in[11];
    const float* Wl_t = (const float*)d_in[12];
    const float* bl_t = (const float*)d_in[13];
    const float* Wr_t = (const float*)d_in[14];
    const float* Wl_s = (const float*)d_in[15];
    const float* bl_s = (const float*)d_in[16];
    const float* Wr_s = (const float*)d_in[17];

    const int n_ip  = in_sizes[0] / H;
    const int n_con = in_sizes[1] / H;
    const int nE_ipcon = in_sizes[2];
    const int nE_conip = in_sizes[4];
    const int nE_ipip  = in_sizes[6];
    const int nE_csrc  = in_sizes[8];
    const int nE_cdst  = in_sizes[10];

    uint32_t *s0, *s1, *s2;
    float *tmpC, *ipA, *ipB, *conA, *conB;
    uint2* wsp;
    int *cnt, *off, *eidx, *part;
    cudaGetSymbolAddress((void**)&s0,   g_s0);
    cudaGetSymbolAddress((void**)&s1,   g_s1);
    cudaGetSymbolAddress((void**)&s2,   g_s2);
    cudaGetSymbolAddress((void**)&tmpC, g_tmpC);
    cudaGetSymbolAddress((void**)&ipA,  g_ipA);
    cudaGetSymbolAddress((void**)&ipB,  g_ipB);
    cudaGetSymbolAddress((void**)&conA, g_conA);
    cudaGetSymbolAddress((void**)&conB, g_conB);
    cudaGetSymbolAddress((void**)&wsp,  g_wsplit);
    cudaGetSymbolAddress((void**)&cnt,  g_cnt);
    cudaGetSymbolAddress((void**)&off,  g_off);
    cudaGetSymbolAddress((void**)&eidx, g_eidx);
    cudaGetSymbolAddress((void**)&part, g_part);

    cudaFuncSetAttribute(combine_fused_kernel, cudaFuncAttributeMaxDynamicSharedMemorySize, DSMEM_BYTES);

    float* out = (float*)d_out;

    BuildParams bp;
    bp.e[0] = { src_ipip,  dst_ipip,  nE_ipip,  n_ip,  0,                0 };
    bp.e[1] = { src_csrc,  dst_csrc,  nE_csrc,  n_con, n_ip,             nE_ipip };
    bp.e[2] = { src_cdst,  dst_cdst,  nE_cdst,  n_con, n_ip + n_con,     nE_ipip + nE_csrc };
    bp.e[3] = { src_ipcon, dst_ipcon, nE_ipcon, n_con, n_ip + 2 * n_con, nE_ipip + nE_csrc + nE_cdst };
    bp.e[4] = { src_conip, dst_conip, nE_conip, n_ip,  n_ip + 3 * n_con, nE_ipip + nE_csrc + nE_cdst + nE_ipcon };

    int maxE = nE_ipip;
    if (nE_csrc  > maxE) maxE = nE_csrc;
    if (nE_cdst  > maxE) maxE = nE_cdst;
    if (nE_ipcon > maxE) maxE = nE_ipcon;
    if (nE_conip > maxE) maxE = nE_conip;
    const int cntBlocks = (maxE + 255) / 256;

    precount_kernel<<<640 + 5 * cntBlocks, 256>>>(Wl_t, Wr_t, Wl_s, Wr_s, wsp, bp, cnt, cntBlocks);
    scan_phase1<<<dim3(MAXB, 5), 1024>>>(bp, cnt, off, part);
    scan_phase23<<<dim3(MAXB, 5), 1024>>>(bp, off, part);
    fill_kernel<<<dim3(cntBlocks, 5), 256>>>(bp, cnt, off, eidx);

    const int* off0 = off + bp.e[0].dstbase + 0;
    const int* off1 = off + bp.e[1].dstbase + 1;
    const int* off2 = off + bp.e[2].dstbase + 2;
    const int* off3 = off + bp.e[3].dstbase + 3;
    const int* off4 = off + bp.e[4].dstbase + 4;
    const int* ei0 = eidx + bp.e[0].ebase;
    const int* ei1 = eidx + bp.e[1].ebase;
    const int* ei2 = eidx + bp.e[2].ebase;
    const int* ei3 = eidx + bp.e[3].ebase;
    const int* ei4 = eidx + bp.e[4].ebase;

    const int nbIP  = (n_ip  + 255) / 256;
    const int nbCON = (n_con + 255) / 256;
    const int aggBlocksCon = (n_con * 32 + 255) / 256;
    const size_t WSZ = 16384;

    for (int l = 0; l < 2; l++) {
        const float* xi = (l == 0) ? x_ip  : ipB;
        const float* xc = (l == 0) ? x_con : conB;

        const float* b0 = bl_t + (size_t)(l * 3 + 0) * H;
        const float* b1 = bl_t + (size_t)(l * 3 + 1) * H;
        const float* b2 = bl_t + (size_t)(l * 3 + 2) * H;
        const float* bs0 = bl_s + (size_t)(l * 2 + 0) * H;
        const float* bs1 = bl_s + (size_t)(l * 2 + 1) * H;

        // ---------- temporal aggregation (3 segments, fused) ----------
        AggSeg a0 = { xi, off0, ei0, s0, n_ip };
        AggSeg a1 = { xc, off1, ei1, s1, n_con };
        AggSeg a2 = { xc, off2, ei2, s2, n_con };
        agg_fused_kernel<<<dim3(aggBlocksCon, 3), 256>>>(a0, a1, a2);

        // ---------- temporal combines: (ip sage + con sage1) fused, then con sage2 ----------
        CombSeg cIP = { s0, xi, wsp + (size_t)(l * 3 + 0) * WSZ, b0, nullptr, ipA,  n_ip,  nbIP,  1 };
        CombSeg cC1 = { s1, xc, wsp + (size_t)(l * 3 + 1) * WSZ, b1, nullptr, tmpC, n_con, nbCON, 0 };
        combine_fused_kernel<<<nbIP + nbCON, 512, DSMEM_BYTES>>>(cIP, cC1);

        CombSeg cC2 = { s2, xc, wsp + (size_t)(l * 3 + 2) * WSZ, b2, tmpC, conA, n_con, nbCON, 2 };
        CombSeg cNil = {};
        combine_fused_kernel<<<nbCON, 512, DSMEM_BYTES>>>(cC2, cNil);

        // ---------- spatial aggregation (2 segments, fused) ----------
        AggSeg a3 = { ipA,  off3, ei3, s1, n_con };
        AggSeg a4 = { conA, off4, ei4, s0, n_ip };
        agg_fused_kernel<<<dim3(aggBlocksCon, 2), 256>>>(a3, a4, a4);

        // ---------- spatial combines fused ----------
        float* out_ip  = (l == 1) ? out : ipB;
        float* out_con = (l == 1) ? (out + (size_t)n_ip * H) : conB;

        CombSeg cSC = { s1, conA, wsp + (size_t)(6 + l * 2 + 0) * WSZ, bs0, nullptr, out_con, n_con, nbCON, 1 };
        CombSeg cSI = { s0, ipA,  wsp + (size_t)(6 + l * 2 + 1) * WSZ, bs1, nullptr, out_ip,  n_ip,  nbIP,  1 };
        combine_fused_kernel<<<nbCON + nbIP, 512, DSMEM_BYTES>>>(cSC, cSI);
    }
}

// round 10
// speedup vs baseline: 1.1323x; 1.1301x over previous
#include <cuda_runtime.h>
#include <cuda_bf16.h>
#include <math.h>
#include <stdint.h>

#define H 128
#define N_IP_MAX 50000
#define N_CON_MAX 200000
#define MAXB 256

// ---------------- scratch ----------------
__device__ float g_s0[N_IP_MAX * H];
__device__ float g_s1[N_CON_MAX * H];
__device__ float g_s2[N_CON_MAX * H];
__device__ float g_tmpC[N_CON_MAX * H];
__device__ float g_ipA[N_IP_MAX * H];
__device__ float g_ipB[N_IP_MAX * H];
__device__ float g_conA[N_CON_MAX * H];
__device__ float g_conB[N_CON_MAX * H];
__device__ uint2 g_wsplit[10 * 16384];
__device__ int g_cnt[700032];      // .bss zero; fill counts it back down to zero
__device__ int g_off[700064];
__device__ int g_eidx[1800064];
__device__ int g_part[5 * MAXB];

struct EdgeDesc { const int* src; const int* dst; int nE; int n_dst; int dstbase; int ebase; };
struct BuildParams { EdgeDesc e[5]; };
struct AggSeg { const float* x; const int* off; const int* eidx; float* s; int n; };
struct CombSeg {
    const float* s; const float* xdst; const uint2* w; const float* bb;
    const float* addin; float* out; int n; int nblk; int mode;  // 0 norm,1 +lrelu,2 +addin+lrelu
};

// ---------------- helpers ----------------
__device__ __forceinline__ uint2 split2(float x0, float x1)
{
    uint32_t hi;
    asm("cvt.rn.bf16x2.f32 %0, %1, %2;" : "=r"(hi) : "f"(x1), "f"(x0));
    float h0 = __uint_as_float(hi << 16);
    float h1 = __uint_as_float(hi & 0xffff0000u);
    uint32_t lo;
    asm("cvt.rn.bf16x2.f32 %0, %1, %2;" : "=r"(lo) : "f"(x1 - h1), "f"(x0 - h0));
    return make_uint2(hi, lo);
}

__device__ __forceinline__ void mma16816(float* d, const uint32_t* a, uint32_t b0, uint32_t b1)
{
    asm volatile(
        "mma.sync.aligned.m16n8k16.row.col.f32.bf16.bf16.f32 "
        "{%0,%1,%2,%3}, {%4,%5,%6,%7}, {%8,%9}, {%0,%1,%2,%3};"
        : "+f"(d[0]), "+f"(d[1]), "+f"(d[2]), "+f"(d[3])
        : "r"(a[0]), "r"(a[1]), "r"(a[2]), "r"(a[3]), "r"(b0), "r"(b1));
}

__device__ __forceinline__ void cp_async16(uint32_t smem_dst, const void* gsrc)
{
    asm volatile("cp.async.ca.shared.global [%0], [%1], 16;" :: "r"(smem_dst), "l"(gsrc));
}
__device__ __forceinline__ void cp_commit() { asm volatile("cp.async.commit_group;"); }
__device__ __forceinline__ void cp_wait0()  { asm volatile("cp.async.wait_group 0;" ::: "memory"); }

// ---------------- fused presplit + degree count ----------------
__global__ void precount_kernel(const float* __restrict__ Wl_t, const float* __restrict__ Wr_t,
                                const float* __restrict__ Wl_s, const float* __restrict__ Wr_s,
                                uint2* __restrict__ out, BuildParams bp,
                                int* __restrict__ cnt, int cntBlocks)
{
    int bx = blockIdx.x;
    if (bx < 640) {
        int sg  = bx >> 6;
        int idx = (bx & 63) * 256 + threadIdx.x;
        int p = idx >> 7;
        int col = idx & 127;
        const float *Wl, *Wr;
        if (sg < 6) { Wl = Wl_t + (size_t)sg * H * H;       Wr = Wr_t + (size_t)sg * H * H; }
        else        { Wl = Wl_s + (size_t)(sg - 6) * H * H; Wr = Wr_s + (size_t)(sg - 6) * H * H; }
        int k0 = 2 * p;
        float x0 = (k0 < H)     ? Wl[k0 * H + col]       : Wr[(k0 - H) * H + col];
        float x1 = (k0 + 1 < H) ? Wl[(k0 + 1) * H + col] : Wr[(k0 + 1 - H) * H + col];
        out[(size_t)sg * 16384 + idx] = split2(x0, x1);
    } else {
        int b2 = bx - 640;
        int t = b2 / cntBlocks;
        int i = (b2 % cntBlocks) * 256 + threadIdx.x;
        EdgeDesc d = bp.e[t];
        if (i < d.nE) atomicAdd(&cnt[d.dstbase + d.dst[i]], 1);
    }
}

// ---------------- CSR scans ----------------
__global__ void scan_phase1(BuildParams bp, const int* __restrict__ cnt,
                            int* __restrict__ off, int* __restrict__ part)
{
    int t = blockIdx.y;
    EdgeDesc d = bp.e[t];
    int L = d.n_dst;
    int i = blockIdx.x * 1024 + threadIdx.x;
    __shared__ int sh[1024];
    int v = (i < L) ? cnt[d.dstbase + i] : 0;
    sh[threadIdx.x] = v;
    __syncthreads();
    for (int o = 1; o < 1024; o <<= 1) {
        int x = (threadIdx.x >= o) ? sh[threadIdx.x - o] : 0;
        __syncthreads();
        sh[threadIdx.x] += x;
        __syncthreads();
    }
    if (i < L) off[d.dstbase + t + i] = sh[threadIdx.x] - v;
    if (threadIdx.x == 1023) part[t * MAXB + blockIdx.x] = sh[1023];
}

__global__ void scan_phase23(BuildParams bp, int* __restrict__ off, const int* __restrict__ part)
{
    int t = blockIdx.y;
    EdgeDesc d = bp.e[t];
    int L = d.n_dst;
    __shared__ int pref[MAXB];
    if (threadIdx.x < MAXB) pref[threadIdx.x] = part[t * MAXB + threadIdx.x];
    __syncthreads();
    for (int o = 1; o < MAXB; o <<= 1) {
        int x = 0;
        if (threadIdx.x < MAXB && threadIdx.x >= o) x = pref[threadIdx.x - o];
        __syncthreads();
        if (threadIdx.x < MAXB) pref[threadIdx.x] += x;
        __syncthreads();
    }
    int add = (blockIdx.x == 0) ? 0 : pref[blockIdx.x - 1];
    int i = blockIdx.x * 1024 + threadIdx.x;
    if (i < L) off[d.dstbase + t + i] += add;
    if (blockIdx.x == 0 && threadIdx.x == 0) off[d.dstbase + t + L] = d.nE;
}

// fill: counts cnt back DOWN to zero (self-reinitializing across replays)
__global__ void fill_kernel(BuildParams bp, int* __restrict__ cnt,
                            const int* __restrict__ off, int* __restrict__ eidx)
{
    int t = blockIdx.y;
    EdgeDesc d = bp.e[t];
    int i = blockIdx.x * blockDim.x + threadIdx.x;
    if (i >= d.nE) return;
    int dd = d.dst[i];
    int pos = off[d.dstbase + t + dd] + atomicAdd(&cnt[d.dstbase + dd], -1) - 1;
    eidx[d.ebase + pos] = d.src[i];
}

// ---------------- fused CSR mean-aggregation (up to 3 segments) ----------------
__global__ void agg_fused_kernel(AggSeg a0, AggSeg a1, AggSeg a2)
{
    AggSeg sg;
    if (blockIdx.y == 0) sg = a0;
    else if (blockIdx.y == 1) sg = a1;
    else sg = a2;
    int w = (blockIdx.x * blockDim.x + threadIdx.x) >> 5;
    int lane = threadIdx.x & 31;
    if (w >= sg.n) return;
    int start = sg.off[w], end = sg.off[w + 1];
    float4 acc = make_float4(0.f, 0.f, 0.f, 0.f);
    for (int e = start; e < end; e++) {
        int si = __ldg(sg.eidx + e);
        float4 v = reinterpret_cast<const float4*>(sg.x)[(size_t)si * 32 + lane];
        acc.x += v.x; acc.y += v.y; acc.z += v.z; acc.w += v.w;
    }
    float inv = 1.0f / (float)max(end - start, 1);
    acc.x *= inv; acc.y *= inv; acc.z *= inv; acc.w *= inv;
    reinterpret_cast<float4*>(sg.s)[(size_t)w * 32 + lane] = acc;
}

// ---------------- fused SAGE combine (mma.sync, 3x-bf16 split, W fully staged) --------
#define ASTRIDE 16
#define WSTRIDE 264
#define DSMEM_BYTES ((2 * 256 * ASTRIDE + 128 * WSTRIDE) * 4)

__global__ void __launch_bounds__(512) combine_fused_kernel(CombSeg A, CombSeg B)
{
    extern __shared__ uint32_t dyn[];
    uint32_t* Asm0 = dyn;
    uint32_t* Asm1 = dyn + 256 * ASTRIDE;
    uint32_t* Wsm  = dyn + 2 * 256 * ASTRIDE;
    __shared__ float ssred[256];

    CombSeg cs;
    int blk = blockIdx.x;
    if (blk < A.nblk) cs = A;
    else { blk -= A.nblk; cs = B; }

    const int tid  = threadIdx.x;
    const int row0 = blk * 256;
    const int n    = cs.n;
    const int mode = cs.mode;

    // one-shot W stage
    {
        uint32_t wb = (uint32_t)__cvta_generic_to_shared(Wsm);
#pragma unroll
        for (int it = 0; it < 16; it++) {
            int ch = tid + it * 512;
            int p = ch >> 6, o = ch & 63;
            cp_async16(wb + (uint32_t)(p * WSTRIDE + o * 4) * 4, cs.w + p * 128 + o * 2);
        }
        cp_commit();
    }
    if (tid < 256) ssred[tid] = 0.0f;

    // ---- A producer mapping ----
    const int ar   = tid >> 1;
    const int half = tid & 1;
    const int grow = row0 + ar;
    const bool rowok = grow < n;

    float af[8];
    auto load_a = [&](int kt) {
        int k0 = kt * 16 + half * 8;
        const float* ap = (k0 < H) ? (cs.s + (size_t)grow * H + k0)
                                   : (cs.xdst + (size_t)grow * H + (k0 - H));
        float4 f0 = make_float4(0.f, 0.f, 0.f, 0.f), f1 = f0;
        if (rowok) {
            f0 = *reinterpret_cast<const float4*>(ap);
            f1 = *reinterpret_cast<const float4*>(ap + 4);
        }
        af[0] = f0.x; af[1] = f0.y; af[2] = f0.z; af[3] = f0.w;
        af[4] = f1.x; af[5] = f1.y; af[6] = f1.z; af[7] = f1.w;
    };

    auto store_a = [&](uint32_t* buf) {
#pragma unroll
        for (int j = 0; j < 4; j++) {
            int p = half * 4 + j;
            int q = (p < 4) ? (2 * p) : (2 * (p - 4) + 1);
            uint2 v = split2(af[2 * j], af[2 * j + 1]);
            *reinterpret_cast<uint2*>(&buf[ar * ASTRIDE + 2 * q]) = v;
        }
    };

    // ---- mma mapping ----
    const int lane = tid & 31;
    const int wid  = tid >> 5;
    const int wm   = wid >> 2;
    const int wn   = wid & 3;
    const int g    = lane >> 2;
    const int c    = lane & 3;

    float acc[4][4][4];
#pragma unroll
    for (int mt = 0; mt < 4; mt++)
#pragma unroll
        for (int nt = 0; nt < 4; nt++)
#pragma unroll
            for (int j = 0; j < 4; j++) acc[mt][nt][j] = 0.0f;

    load_a(0);
    store_a(Asm0);
    cp_wait0();
    __syncthreads();

    for (int kt = 0; kt < 16; kt++) {
        uint32_t* cur = (kt & 1) ? Asm1 : Asm0;
        uint32_t* nxt = (kt & 1) ? Asm0 : Asm1;
        if (kt < 15) load_a(kt + 1);

        uint32_t ahf[4][4], alf[4][4];
#pragma unroll
        for (int mt = 0; mt < 4; mt++) {
            int R = wm * 64 + mt * 16;
            uint4 v0 = *reinterpret_cast<const uint4*>(&cur[(R + g) * ASTRIDE + c * 4]);
            uint4 v1 = *reinterpret_cast<const uint4*>(&cur[(R + g + 8) * ASTRIDE + c * 4]);
            ahf[mt][0] = v0.x; ahf[mt][1] = v1.x; ahf[mt][2] = v0.z; ahf[mt][3] = v1.z;
            alf[mt][0] = v0.y; alf[mt][1] = v1.y; alf[mt][2] = v0.w; alf[mt][3] = v1.w;
        }
#pragma unroll
        for (int nt = 0; nt < 4; nt++) {
            int col = wn * 32 + nt * 8 + g;
            uint2 w0 = *reinterpret_cast<const uint2*>(&Wsm[(kt * 8 + c) * WSTRIDE + col * 2]);
            uint2 w1 = *reinterpret_cast<const uint2*>(&Wsm[(kt * 8 + c + 4) * WSTRIDE + col * 2]);
#pragma unroll
            for (int mt = 0; mt < 4; mt++) {
                mma16816(acc[mt][nt], ahf[mt], w0.x, w1.x);
                mma16816(acc[mt][nt], ahf[mt], w0.y, w1.y);
                mma16816(acc[mt][nt], alf[mt], w0.x, w1.x);
            }
        }

        if (kt < 15) store_a(nxt);
        __syncthreads();
    }

    // ---- epilogue ----
#pragma unroll
    for (int mt = 0; mt < 4; mt++) {
        float ss0 = 0.0f, ss1 = 0.0f;
#pragma unroll
        for (int nt = 0; nt < 4; nt++) {
            int col = wn * 32 + nt * 8 + c * 2;
            float b0v = __ldg(cs.bb + col), b1v = __ldg(cs.bb + col + 1);
            acc[mt][nt][0] += b0v; acc[mt][nt][1] += b1v;
            acc[mt][nt][2] += b0v; acc[mt][nt][3] += b1v;
            ss0 += acc[mt][nt][0] * acc[mt][nt][0] + acc[mt][nt][1] * acc[mt][nt][1];
            ss1 += acc[mt][nt][2] * acc[mt][nt][2] + acc[mt][nt][3] * acc[mt][nt][3];
        }
        ss0 += __shfl_xor_sync(0xffffffffu, ss0, 1);
        ss0 += __shfl_xor_sync(0xffffffffu, ss0, 2);
        ss1 += __shfl_xor_sync(0xffffffffu, ss1, 1);
        ss1 += __shfl_xor_sync(0xffffffffu, ss1, 2);
        if (c == 0) {
            atomicAdd(&ssred[wm * 64 + mt * 16 + g],     ss0);
            atomicAdd(&ssred[wm * 64 + mt * 16 + 8 + g], ss1);
        }
    }
    __syncthreads();

#pragma unroll
    for (int mt = 0; mt < 4; mt++) {
        int rl0 = wm * 64 + mt * 16 + g;
        int rl1 = rl0 + 8;
        float inv0 = 1.0f / fmaxf(sqrtf(ssred[rl0]), 1e-12f);
        float inv1 = 1.0f / fmaxf(sqrtf(ssred[rl1]), 1e-12f);
        int gr0 = row0 + rl0;
        int gr1 = row0 + rl1;
#pragma unroll
        for (int nt = 0; nt < 4; nt++) {
            int col = wn * 32 + nt * 8 + c * 2;
            if (gr0 < n) {
                float v0 = acc[mt][nt][0] * inv0;
                float v1 = acc[mt][nt][1] * inv0;
                if (mode == 2) {
                    float2 a2 = *reinterpret_cast<const float2*>(cs.addin + (size_t)gr0 * H + col);
                    v0 += a2.x; v1 += a2.y;
                }
                if (mode >= 1) {
                    v0 = (v0 >= 0.f) ? v0 : 0.01f * v0;
                    v1 = (v1 >= 0.f) ? v1 : 0.01f * v1;
                }
                *reinterpret_cast<float2*>(cs.out + (size_t)gr0 * H + col) = make_float2(v0, v1);
            }
            if (gr1 < n) {
                float v2 = acc[mt][nt][2] * inv1;
                float v3 = acc[mt][nt][3] * inv1;
                if (mode == 2) {
                    float2 a2 = *reinterpret_cast<const float2*>(cs.addin + (size_t)gr1 * H + col);
                    v2 += a2.x; v3 += a2.y;
                }
                if (mode >= 1) {
                    v2 = (v2 >= 0.f) ? v2 : 0.01f * v2;
                    v3 = (v3 >= 0.f) ? v3 : 0.01f * v3;
                }
                *reinterpret_cast<float2*>(cs.out + (size_t)gr1 * H + col) = make_float2(v2, v3);
            }
        }
    }
}

// ---------------- host ----------------
extern "C" void kernel_launch(void* const* d_in, const int* in_sizes, int n_in,
                              void* d_out, int out_size)
{
    const float* x_ip  = (const float*)d_in[0];
    const float* x_con = (const float*)d_in[1];
    const int* src_ipcon = (const int*)d_in[2];
    const int* dst_ipcon = (const int*)d_in[3];
    const int* src_conip = (const int*)d_in[4];
    const int* dst_conip = (const int*)d_in[5];
    const int* src_ipip  = (const int*)d_in[6];
    const int* dst_ipip  = (const int*)d_in[7];
    const int* src_csrc  = (const int*)d_in[8];
    const int* dst_csrc  = (const int*)d_in[9];
    const int* src_cdst  = (const int*)d_in[10];
    const int* dst_cdst  = (const int*)d_in[11];
    const float* Wl_t = (const float*)d_in[12];
    const float* bl_t = (const float*)d_in[13];
    const float* Wr_t = (const float*)d_in[14];
    const float* Wl_s = (const float*)d_in[15];
    const float* bl_s = (const float*)d_in[16];
    const float* Wr_s = (const float*)d_in[17];

    const int n_ip  = in_sizes[0] / H;
    const int n_con = in_sizes[1] / H;
    const int nE_ipcon = in_sizes[2];
    const int nE_conip = in_sizes[4];
    const int nE_ipip  = in_sizes[6];
    const int nE_csrc  = in_sizes[8];
    const int nE_cdst  = in_sizes[10];

    float *s0, *s1, *s2, *tmpC, *ipA, *ipB, *conA, *conB;
    uint2* wsp;
    int *cnt, *off, *eidx, *part;
    cudaGetSymbolAddress((void**)&s0,   g_s0);
    cudaGetSymbolAddress((void**)&s1,   g_s1);
    cudaGetSymbolAddress((void**)&s2,   g_s2);
    cudaGetSymbolAddress((void**)&tmpC, g_tmpC);
    cudaGetSymbolAddress((void**)&ipA,  g_ipA);
    cudaGetSymbolAddress((void**)&ipB,  g_ipB);
    cudaGetSymbolAddress((void**)&conA, g_conA);
    cudaGetSymbolAddress((void**)&conB, g_conB);
    cudaGetSymbolAddress((void**)&wsp,  g_wsplit);
    cudaGetSymbolAddress((void**)&cnt,  g_cnt);
    cudaGetSymbolAddress((void**)&off,  g_off);
    cudaGetSymbolAddress((void**)&eidx, g_eidx);
    cudaGetSymbolAddress((void**)&part, g_part);

    cudaFuncSetAttribute(combine_fused_kernel, cudaFuncAttributeMaxDynamicSharedMemorySize, DSMEM_BYTES);

    float* out = (float*)d_out;

    BuildParams bp;
    bp.e[0] = { src_ipip,  dst_ipip,  nE_ipip,  n_ip,  0,                0 };
    bp.e[1] = { src_csrc,  dst_csrc,  nE_csrc,  n_con, n_ip,             nE_ipip };
    bp.e[2] = { src_cdst,  dst_cdst,  nE_cdst,  n_con, n_ip + n_con,     nE_ipip + nE_csrc };
    bp.e[3] = { src_ipcon, dst_ipcon, nE_ipcon, n_con, n_ip + 2 * n_con, nE_ipip + nE_csrc + nE_cdst };
    bp.e[4] = { src_conip, dst_conip, nE_conip, n_ip,  n_ip + 3 * n_con, nE_ipip + nE_csrc + nE_cdst + nE_ipcon };

    int maxE = nE_ipip;
    if (nE_csrc  > maxE) maxE = nE_csrc;
    if (nE_cdst  > maxE) maxE = nE_cdst;
    if (nE_ipcon > maxE) maxE = nE_ipcon;
    if (nE_conip > maxE) maxE = nE_conip;
    const int cntBlocks = (maxE + 255) / 256;

    precount_kernel<<<640 + 5 * cntBlocks, 256>>>(Wl_t, Wr_t, Wl_s, Wr_s, wsp, bp, cnt, cntBlocks);
    scan_phase1<<<dim3(MAXB, 5), 1024>>>(bp, cnt, off, part);
    scan_phase23<<<dim3(MAXB, 5), 1024>>>(bp, off, part);
    fill_kernel<<<dim3(cntBlocks, 5), 256>>>(bp, cnt, off, eidx);

    const int* off0 = off + bp.e[0].dstbase + 0;
    const int* off1 = off + bp.e[1].dstbase + 1;
    const int* off2 = off + bp.e[2].dstbase + 2;
    const int* off3 = off + bp.e[3].dstbase + 3;
    const int* off4 = off + bp.e[4].dstbase + 4;
    const int* ei0 = eidx + bp.e[0].ebase;
    const int* ei1 = eidx + bp.e[1].ebase;
    const int* ei2 = eidx + bp.e[2].ebase;
    const int* ei3 = eidx + bp.e[3].ebase;
    const int* ei4 = eidx + bp.e[4].ebase;

    const int nbIP  = (n_ip  + 255) / 256;
    const int nbCON = (n_con + 255) / 256;
    const int aggBlocksCon = (n_con * 32 + 255) / 256;
    const size_t WSZ = 16384;

    for (int l = 0; l < 2; l++) {
        const float* xi = (l == 0) ? x_ip  : ipB;
        const float* xc = (l == 0) ? x_con : conB;

        const float* b0 = bl_t + (size_t)(l * 3 + 0) * H;
        const float* b1 = bl_t + (size_t)(l * 3 + 1) * H;
        const float* b2 = bl_t + (size_t)(l * 3 + 2) * H;
        const float* bs0 = bl_s + (size_t)(l * 2 + 0) * H;
        const float* bs1 = bl_s + (size_t)(l * 2 + 1) * H;

        // ---------- temporal aggregation (3 segments, fused) ----------
        AggSeg a0 = { xi, off0, ei0, s0, n_ip };
        AggSeg a1 = { xc, off1, ei1, s1, n_con };
        AggSeg a2 = { xc, off2, ei2, s2, n_con };
        agg_fused_kernel<<<dim3(aggBlocksCon, 3), 256>>>(a0, a1, a2);

        // ---------- temporal combines: (con sage1 + ip sage) fused [big first], then con sage2 --
        CombSeg cC1 = { s1, xc, wsp + (size_t)(l * 3 + 1) * WSZ, b1, nullptr, tmpC, n_con, nbCON, 0 };
        CombSeg cIP = { s0, xi, wsp + (size_t)(l * 3 + 0) * WSZ, b0, nullptr, ipA,  n_ip,  nbIP,  1 };
        combine_fused_kernel<<<nbCON + nbIP, 512, DSMEM_BYTES>>>(cC1, cIP);

        CombSeg cC2 = { s2, xc, wsp + (size_t)(l * 3 + 2) * WSZ, b2, tmpC, conA, n_con, nbCON, 2 };
        CombSeg cNil = {};
        combine_fused_kernel<<<nbCON, 512, DSMEM_BYTES>>>(cC2, cNil);

        // ---------- spatial aggregation (2 segments, fused) ----------
        AggSeg a3 = { ipA,  off3, ei3, s1, n_con };
        AggSeg a4 = { conA, off4, ei4, s0, n_ip };
        agg_fused_kernel<<<dim3(aggBlocksCon, 2), 256>>>(a3, a4, a4);

        // ---------- spatial combines fused (big first) ----------
        float* out_ip  = (l == 1) ? out : ipB;
        float* out_con = (l == 1) ? (out + (size_t)n_ip * H) : conB;

        CombSeg cSC = { s1, conA, wsp + (size_t)(6 + l * 2 + 0) * WSZ, bs0, nullptr, out_con, n_con, nbCON, 1 };
        CombSeg cSI = { s0, ipA,  wsp + (size_t)(6 + l * 2 + 1) * WSZ, bs1, nullptr, out_ip,  n_ip,  nbIP,  1 };
        combine_fused_kernel<<<nbCON + nbIP, 512, DSMEM_BYTES>>>(cSC, cSI);
    }
}

// round 11
// speedup vs baseline: 1.2686x; 1.1205x over previous
#include <cuda_runtime.h>
#include <cuda_fp16.h>
#include <math.h>
#include <stdint.h>

#define H 128
#define N_IP_MAX 50000
#define N_CON_MAX 200000
#define MAXB 256

// ---------------- scratch ----------------
__device__ float g_s0[N_IP_MAX * H];
__device__ float g_s1[N_CON_MAX * H];
__device__ float g_s2[N_CON_MAX * H];
__device__ float g_tmpC[N_CON_MAX * H];
__device__ float g_ipA[N_IP_MAX * H];
__device__ float g_ipB[N_IP_MAX * H];
__device__ float g_conA[N_CON_MAX * H];
__device__ float g_conB[N_CON_MAX * H];
__device__ uint2 g_wsplit[10 * 16384];   // per sage: [k-pair][col] (hi,lo) fp16x2
__device__ int g_cnt[700032];            // .bss zero; fill counts it back down to zero
__device__ int g_off[700064];
__device__ int g_eidx[1800064];
__device__ int g_part[5 * MAXB];

struct EdgeDesc { const int* src; const int* dst; int nE; int n_dst; int dstbase; int ebase; };
struct BuildParams { EdgeDesc e[5]; };
struct AggSeg { const float* x; const int* off; const int* eidx; float* s; int n; };
struct CombSeg {
    const float* s; const float* xdst; const uint2* w; const float* bb;
    const float* addin; float* out; int n; int nblk; int mode;  // 0 norm,1 +lrelu,2 +addin+lrelu
};

// ---------------- helpers ----------------
// pack two floats to fp16x2 (single rounding)
__device__ __forceinline__ uint32_t packh2(float x0, float x1)
{
    uint32_t r;
    asm("cvt.rn.f16x2.f32 %0, %1, %2;" : "=r"(r) : "f"(x1), "f"(x0));
    return r;
}

__device__ __forceinline__ void mma16816h(float* d, const uint32_t* a, uint32_t b0, uint32_t b1)
{
    asm volatile(
        "mma.sync.aligned.m16n8k16.row.col.f32.f16.f16.f32 "
        "{%0,%1,%2,%3}, {%4,%5,%6,%7}, {%8,%9}, {%0,%1,%2,%3};"
        : "+f"(d[0]), "+f"(d[1]), "+f"(d[2]), "+f"(d[3])
        : "r"(a[0]), "r"(a[1]), "r"(a[2]), "r"(a[3]), "r"(b0), "r"(b1));
}

__device__ __forceinline__ void cp_async16(uint32_t smem_dst, const void* gsrc)
{
    asm volatile("cp.async.ca.shared.global [%0], [%1], 16;" :: "r"(smem_dst), "l"(gsrc));
}
__device__ __forceinline__ void cp_commit() { asm volatile("cp.async.commit_group;"); }
__device__ __forceinline__ void cp_wait0()  { asm volatile("cp.async.wait_group 0;" ::: "memory"); }

// slot permutation for pair p in [0,8): [0,4,1,5,2,6,3,7]
__device__ __forceinline__ int permq(int p) { return (p < 4) ? (2 * p) : (2 * (p - 4) + 1); }

// ---------------- fused presplit (fp16 2-term W) + degree count ----------------
__global__ void precount_kernel(const float* __restrict__ Wl_t, const float* __restrict__ Wr_t,
                                const float* __restrict__ Wl_s, const float* __restrict__ Wr_s,
                                uint2* __restrict__ out, BuildParams bp,
                                int* __restrict__ cnt, int cntBlocks)
{
    int bx = blockIdx.x;
    if (bx < 640) {
        int sg  = bx >> 6;
        int idx = (bx & 63) * 256 + threadIdx.x;
        int p = idx >> 7;
        int col = idx & 127;
        const float *Wl, *Wr;
        if (sg < 6) { Wl = Wl_t + (size_t)sg * H * H;       Wr = Wr_t + (size_t)sg * H * H; }
        else        { Wl = Wl_s + (size_t)(sg - 6) * H * H; Wr = Wr_s + (size_t)(sg - 6) * H * H; }
        int k0 = 2 * p;
        float x0 = (k0 < H)     ? Wl[k0 * H + col]       : Wr[(k0 - H) * H + col];
        float x1 = (k0 + 1 < H) ? Wl[(k0 + 1) * H + col] : Wr[(k0 + 1 - H) * H + col];
        __half h0 = __float2half_rn(x0), h1 = __float2half_rn(x1);
        float r0 = x0 - __half2float(h0), r1 = x1 - __half2float(h1);
        __half l0 = __float2half_rn(r0), l1 = __float2half_rn(r1);
        uint32_t hi = (uint32_t)__half_as_ushort(h0) | ((uint32_t)__half_as_ushort(h1) << 16);
        uint32_t lo = (uint32_t)__half_as_ushort(l0) | ((uint32_t)__half_as_ushort(l1) << 16);
        out[(size_t)sg * 16384 + idx] = make_uint2(hi, lo);
    } else {
        int b2 = bx - 640;
        int t = b2 / cntBlocks;
        int i = (b2 % cntBlocks) * 256 + threadIdx.x;
        EdgeDesc d = bp.e[t];
        if (i < d.nE) atomicAdd(&cnt[d.dstbase + d.dst[i]], 1);
    }
}

// ---------------- CSR scans ----------------
__global__ void scan_phase1(BuildParams bp, const int* __restrict__ cnt,
                            int* __restrict__ off, int* __restrict__ part)
{
    int t = blockIdx.y;
    EdgeDesc d = bp.e[t];
    int L = d.n_dst;
    int i = blockIdx.x * 1024 + threadIdx.x;
    __shared__ int sh[1024];
    int v = (i < L) ? cnt[d.dstbase + i] : 0;
    sh[threadIdx.x] = v;
    __syncthreads();
    for (int o = 1; o < 1024; o <<= 1) {
        int x = (threadIdx.x >= o) ? sh[threadIdx.x - o] : 0;
        __syncthreads();
        sh[threadIdx.x] += x;
        __syncthreads();
    }
    if (i < L) off[d.dstbase + t + i] = sh[threadIdx.x] - v;
    if (threadIdx.x == 1023) part[t * MAXB + blockIdx.x] = sh[1023];
}

__global__ void scan_phase23(BuildParams bp, int* __restrict__ off, const int* __restrict__ part)
{
    int t = blockIdx.y;
    EdgeDesc d = bp.e[t];
    int L = d.n_dst;
    __shared__ int pref[MAXB];
    if (threadIdx.x < MAXB) pref[threadIdx.x] = part[t * MAXB + threadIdx.x];
    __syncthreads();
    for (int o = 1; o < MAXB; o <<= 1) {
        int x = 0;
        if (threadIdx.x < MAXB && threadIdx.x >= o) x = pref[threadIdx.x - o];
        __syncthreads();
        if (threadIdx.x < MAXB) pref[threadIdx.x] += x;
        __syncthreads();
    }
    int add = (blockIdx.x == 0) ? 0 : pref[blockIdx.x - 1];
    int i = blockIdx.x * 1024 + threadIdx.x;
    if (i < L) off[d.dstbase + t + i] += add;
    if (blockIdx.x == 0 && threadIdx.x == 0) off[d.dstbase + t + L] = d.nE;
}

// fill: counts cnt back DOWN to zero (self-reinitializing across replays)
__global__ void fill_kernel(BuildParams bp, int* __restrict__ cnt,
                            const int* __restrict__ off, int* __restrict__ eidx)
{
    int t = blockIdx.y;
    EdgeDesc d = bp.e[t];
    int i = blockIdx.x * blockDim.x + threadIdx.x;
    if (i >= d.nE) return;
    int dd = d.dst[i];
    int pos = off[d.dstbase + t + dd] + atomicAdd(&cnt[d.dstbase + dd], -1) - 1;
    eidx[d.ebase + pos] = d.src[i];
}

// ---------------- fused CSR mean-aggregation (up to 3 segments) ----------------
__global__ void agg_fused_kernel(AggSeg a0, AggSeg a1, AggSeg a2)
{
    AggSeg sg;
    if (blockIdx.y == 0) sg = a0;
    else if (blockIdx.y == 1) sg = a1;
    else sg = a2;
    int w = (blockIdx.x * blockDim.x + threadIdx.x) >> 5;
    int lane = threadIdx.x & 31;
    if (w >= sg.n) return;
    int start = sg.off[w], end = sg.off[w + 1];
    float4 acc = make_float4(0.f, 0.f, 0.f, 0.f);
    for (int e = start; e < end; e++) {
        int si = __ldg(sg.eidx + e);
        float4 v = reinterpret_cast<const float4*>(sg.x)[(size_t)si * 32 + lane];
        acc.x += v.x; acc.y += v.y; acc.z += v.z; acc.w += v.w;
    }
    float inv = 1.0f / (float)max(end - start, 1);
    acc.x *= inv; acc.y *= inv; acc.z *= inv; acc.w *= inv;
    reinterpret_cast<float4*>(sg.s)[(size_t)w * 32 + lane] = acc;
}

// ---------------- fused SAGE combine (fp16 2-term: A*Wh + A*Wl) ----------------
// A smem: [256 rows][8 slots u32 fp16x2, permuted], stride 8. W smem: (hi,lo) pairs as before.
#define ASTRIDE 8
#define WSTRIDE 264
#define DSMEM_BYTES ((2 * 256 * ASTRIDE + 128 * WSTRIDE) * 4)

__global__ void __launch_bounds__(512) combine_fused_kernel(CombSeg A, CombSeg B)
{
    extern __shared__ uint32_t dyn[];
    uint32_t* Asm0 = dyn;
    uint32_t* Asm1 = dyn + 256 * ASTRIDE;
    uint32_t* Wsm  = dyn + 2 * 256 * ASTRIDE;
    __shared__ float ssred[256];

    CombSeg cs;
    int blk = blockIdx.x;
    if (blk < A.nblk) cs = A;
    else { blk -= A.nblk; cs = B; }

    const int tid  = threadIdx.x;
    const int row0 = blk * 256;
    const int n    = cs.n;
    const int mode = cs.mode;

    // one-shot W stage
    {
        uint32_t wb = (uint32_t)__cvta_generic_to_shared(Wsm);
#pragma unroll
        for (int it = 0; it < 16; it++) {
            int ch = tid + it * 512;
            int p = ch >> 6, o = ch & 63;
            cp_async16(wb + (uint32_t)(p * WSTRIDE + o * 4) * 4, cs.w + p * 128 + o * 2);
        }
        cp_commit();
    }
    if (tid < 256) ssred[tid] = 0.0f;

    // ---- A producer mapping ----
    const int ar   = tid >> 1;
    const int half = tid & 1;
    const int grow = row0 + ar;
    const bool rowok = grow < n;

    float af[8];
    auto load_a = [&](int kt) {
        int k0 = kt * 16 + half * 8;
        const float* ap = (k0 < H) ? (cs.s + (size_t)grow * H + k0)
                                   : (cs.xdst + (size_t)grow * H + (k0 - H));
        float4 f0 = make_float4(0.f, 0.f, 0.f, 0.f), f1 = f0;
        if (rowok) {
            f0 = *reinterpret_cast<const float4*>(ap);
            f1 = *reinterpret_cast<const float4*>(ap + 4);
        }
        af[0] = f0.x; af[1] = f0.y; af[2] = f0.z; af[3] = f0.w;
        af[4] = f1.x; af[5] = f1.y; af[6] = f1.z; af[7] = f1.w;
    };

    auto store_a = [&](uint32_t* buf) {
#pragma unroll
        for (int j = 0; j < 4; j++) {
            int p = half * 4 + j;
            buf[ar * ASTRIDE + permq(p)] = packh2(af[2 * j], af[2 * j + 1]);
        }
    };

    // ---- mma mapping ----
    const int lane = tid & 31;
    const int wid  = tid >> 5;
    const int wm   = wid >> 2;
    const int wn   = wid & 3;
    const int g    = lane >> 2;
    const int c    = lane & 3;

    float acc[4][4][4];
#pragma unroll
    for (int mt = 0; mt < 4; mt++)
#pragma unroll
        for (int nt = 0; nt < 4; nt++)
#pragma unroll
            for (int j = 0; j < 4; j++) acc[mt][nt][j] = 0.0f;

    load_a(0);
    store_a(Asm0);
    cp_wait0();
    __syncthreads();

    for (int kt = 0; kt < 16; kt++) {
        uint32_t* cur = (kt & 1) ? Asm1 : Asm0;
        uint32_t* nxt = (kt & 1) ? Asm0 : Asm1;
        if (kt < 15) load_a(kt + 1);

        uint32_t ahf[4][4];
#pragma unroll
        for (int mt = 0; mt < 4; mt++) {
            int R = wm * 64 + mt * 16;
            uint2 v0 = *reinterpret_cast<const uint2*>(&cur[(R + g) * ASTRIDE + c * 2]);
            uint2 v1 = *reinterpret_cast<const uint2*>(&cur[(R + g + 8) * ASTRIDE + c * 2]);
            ahf[mt][0] = v0.x; ahf[mt][1] = v1.x; ahf[mt][2] = v0.y; ahf[mt][3] = v1.y;
        }
#pragma unroll
        for (int nt = 0; nt < 4; nt++) {
            int col = wn * 32 + nt * 8 + g;
            uint2 w0 = *reinterpret_cast<const uint2*>(&Wsm[(kt * 8 + c) * WSTRIDE + col * 2]);
            uint2 w1 = *reinterpret_cast<const uint2*>(&Wsm[(kt * 8 + c + 4) * WSTRIDE + col * 2]);
#pragma unroll
            for (int mt = 0; mt < 4; mt++) {
                mma16816h(acc[mt][nt], ahf[mt], w0.x, w1.x);   // A * Wh
                mma16816h(acc[mt][nt], ahf[mt], w0.y, w1.y);   // A * Wl
            }
        }

        if (kt < 15) store_a(nxt);
        __syncthreads();
    }

    // ---- epilogue ----
#pragma unroll
    for (int mt = 0; mt < 4; mt++) {
        float ss0 = 0.0f, ss1 = 0.0f;
#pragma unroll
        for (int nt = 0; nt < 4; nt++) {
            int col = wn * 32 + nt * 8 + c * 2;
            float b0v = __ldg(cs.bb + col), b1v = __ldg(cs.bb + col + 1);
            acc[mt][nt][0] += b0v; acc[mt][nt][1] += b1v;
            acc[mt][nt][2] += b0v; acc[mt][nt][3] += b1v;
            ss0 += acc[mt][nt][0] * acc[mt][nt][0] + acc[mt][nt][1] * acc[mt][nt][1];
            ss1 += acc[mt][nt][2] * acc[mt][nt][2] + acc[mt][nt][3] * acc[mt][nt][3];
        }
        ss0 += __shfl_xor_sync(0xffffffffu, ss0, 1);
        ss0 += __shfl_xor_sync(0xffffffffu, ss0, 2);
        ss1 += __shfl_xor_sync(0xffffffffu, ss1, 1);
        ss1 += __shfl_xor_sync(0xffffffffu, ss1, 2);
        if (c == 0) {
            atomicAdd(&ssred[wm * 64 + mt * 16 + g],     ss0);
            atomicAdd(&ssred[wm * 64 + mt * 16 + 8 + g], ss1);
        }
    }
    __syncthreads();

#pragma unroll
    for (int mt = 0; mt < 4; mt++) {
        int rl0 = wm * 64 + mt * 16 + g;
        int rl1 = rl0 + 8;
        float inv0 = 1.0f / fmaxf(sqrtf(ssred[rl0]), 1e-12f);
        float inv1 = 1.0f / fmaxf(sqrtf(ssred[rl1]), 1e-12f);
        int gr0 = row0 + rl0;
        int gr1 = row0 + rl1;
#pragma unroll
        for (int nt = 0; nt < 4; nt++) {
            int col = wn * 32 + nt * 8 + c * 2;
            if (gr0 < n) {
                float v0 = acc[mt][nt][0] * inv0;
                float v1 = acc[mt][nt][1] * inv0;
                if (mode == 2) {
                    float2 a2 = *reinterpret_cast<const float2*>(cs.addin + (size_t)gr0 * H + col);
                    v0 += a2.x; v1 += a2.y;
                }
                if (mode >= 1) {
                    v0 = (v0 >= 0.f) ? v0 : 0.01f * v0;
                    v1 = (v1 >= 0.f) ? v1 : 0.01f * v1;
                }
                *reinterpret_cast<float2*>(cs.out + (size_t)gr0 * H + col) = make_float2(v0, v1);
            }
            if (gr1 < n) {
                float v2 = acc[mt][nt][2] * inv1;
                float v3 = acc[mt][nt][3] * inv1;
                if (mode == 2) {
                    float2 a2 = *reinterpret_cast<const float2*>(cs.addin + (size_t)gr1 * H + col);
                    v2 += a2.x; v3 += a2.y;
                }
                if (mode >= 1) {
                    v2 = (v2 >= 0.f) ? v2 : 0.01f * v2;
                    v3 = (v3 >= 0.f) ? v3 : 0.01f * v3;
                }
                *reinterpret_cast<float2*>(cs.out + (size_t)gr1 * H + col) = make_float2(v2, v3);
            }
        }
    }
}

// ---------------- host ----------------
extern "C" void kernel_launch(void* const* d_in, const int* in_sizes, int n_in,
                              void* d_out, int out_size)
{
    const float* x_ip  = (const float*)d_in[0];
    const float* x_con = (const float*)d_in[1];
    const int* src_ipcon = (const int*)d_in[2];
    const int* dst_ipcon = (const int*)d_in[3];
    const int* src_conip = (const int*)d_in[4];
    const int* dst_conip = (const int*)d_in[5];
    const int* src_ipip  = (const int*)d_in[6];
    const int* dst_ipip  = (const int*)d_in[7];
    const int* src_csrc  = (const int*)d_in[8];
    const int* dst_csrc  = (const int*)d_in[9];
    const int* src_cdst  = (const int*)d_in[10];
    const int* dst_cdst  = (const int*)d_in[11];
    const float* Wl_t = (const float*)d_in[12];
    const float* bl_t = (const float*)d_in[13];
    const float* Wr_t = (const float*)d_in[14];
    const float* Wl_s = (const float*)d_in[15];
    const float* bl_s = (const float*)d_in[16];
    const float* Wr_s = (const float*)d_in[17];

    const int n_ip  = in_sizes[0] / H;
    const int n_con = in_sizes[1] / H;
    const int nE_ipcon = in_sizes[2];
    const int nE_conip = in_sizes[4];
    const int nE_ipip  = in_sizes[6];
    const int nE_csrc  = in_sizes[8];
    const int nE_cdst  = in_sizes[10];

    float *s0, *s1, *s2, *tmpC, *ipA, *ipB, *conA, *conB;
    uint2* wsp;
    int *cnt, *off, *eidx, *part;
    cudaGetSymbolAddress((void**)&s0,   g_s0);
    cudaGetSymbolAddress((void**)&s1,   g_s1);
    cudaGetSymbolAddress((void**)&s2,   g_s2);
    cudaGetSymbolAddress((void**)&tmpC, g_tmpC);
    cudaGetSymbolAddress((void**)&ipA,  g_ipA);
    cudaGetSymbolAddress((void**)&ipB,  g_ipB);
    cudaGetSymbolAddress((void**)&conA, g_conA);
    cudaGetSymbolAddress((void**)&conB, g_conB);
    cudaGetSymbolAddress((void**)&wsp,  g_wsplit);
    cudaGetSymbolAddress((void**)&cnt,  g_cnt);
    cudaGetSymbolAddress((void**)&off,  g_off);
    cudaGetSymbolAddress((void**)&eidx, g_eidx);
    cudaGetSymbolAddress((void**)&part, g_part);

    cudaFuncSetAttribute(combine_fused_kernel, cudaFuncAttributeMaxDynamicSharedMemorySize, DSMEM_BYTES);

    float* out = (float*)d_out;

    BuildParams bp;
    bp.e[0] = { src_ipip,  dst_ipip,  nE_ipip,  n_ip,  0,                0 };
    bp.e[1] = { src_csrc,  dst_csrc,  nE_csrc,  n_con, n_ip,             nE_ipip };
    bp.e[2] = { src_cdst,  dst_cdst,  nE_cdst,  n_con, n_ip + n_con,     nE_ipip + nE_csrc };
    bp.e[3] = { src_ipcon, dst_ipcon, nE_ipcon, n_con, n_ip + 2 * n_con, nE_ipip + nE_csrc + nE_cdst };
    bp.e[4] = { src_conip, dst_conip, nE_conip, n_ip,  n_ip + 3 * n_con, nE_ipip + nE_csrc + nE_cdst + nE_ipcon };

    int maxE = nE_ipip;
    if (nE_csrc  > maxE) maxE = nE_csrc;
    if (nE_cdst  > maxE) maxE = nE_cdst;
    if (nE_ipcon > maxE) maxE = nE_ipcon;
    if (nE_conip > maxE) maxE = nE_conip;
    const int cntBlocks = (maxE + 255) / 256;

    precount_kernel<<<640 + 5 * cntBlocks, 256>>>(Wl_t, Wr_t, Wl_s, Wr_s, wsp, bp, cnt, cntBlocks);
    scan_phase1<<<dim3(MAXB, 5), 1024>>>(bp, cnt, off, part);
    scan_phase23<<<dim3(MAXB, 5), 1024>>>(bp, off, part);
    fill_kernel<<<dim3(cntBlocks, 5), 256>>>(bp, cnt, off, eidx);

    const int* off0 = off + bp.e[0].dstbase + 0;
    const int* off1 = off + bp.e[1].dstbase + 1;
    const int* off2 = off + bp.e[2].dstbase + 2;
    const int* off3 = off + bp.e[3].dstbase + 3;
    const int* off4 = off + bp.e[4].dstbase + 4;
    const int* ei0 = eidx + bp.e[0].ebase;
    const int* ei1 = eidx + bp.e[1].ebase;
    const int* ei2 = eidx + bp.e[2].ebase;
    const int* ei3 = eidx + bp.e[3].ebase;
    const int* ei4 = eidx + bp.e[4].ebase;

    const int nbIP  = (n_ip  + 255) / 256;
    const int nbCON = (n_con + 255) / 256;
    const int aggBlocksCon = (n_con * 32 + 255) / 256;
    const size_t WSZ = 16384;

    for (int l = 0; l < 2; l++) {
        const float* xi = (l == 0) ? x_ip  : ipB;
        const float* xc = (l == 0) ? x_con : conB;

        const float* b0 = bl_t + (size_t)(l * 3 + 0) * H;
        const float* b1 = bl_t + (size_t)(l * 3 + 1) * H;
        const float* b2 = bl_t + (size_t)(l * 3 + 2) * H;
        const float* bs0 = bl_s + (size_t)(l * 2 + 0) * H;
        const float* bs1 = bl_s + (size_t)(l * 2 + 1) * H;

        // ---------- temporal aggregation (3 segments, fused) ----------
        AggSeg a0 = { xi, off0, ei0, s0, n_ip };
        AggSeg a1 = { xc, off1, ei1, s1, n_con };
        AggSeg a2 = { xc, off2, ei2, s2, n_con };
        agg_fused_kernel<<<dim3(aggBlocksCon, 3), 256>>>(a0, a1, a2);

        // ---------- temporal combines: (con sage1 + ip sage) fused, then con sage2 ----------
        CombSeg cC1 = { s1, xc, wsp + (size_t)(l * 3 + 1) * WSZ, b1, nullptr, tmpC, n_con, nbCON, 0 };
        CombSeg cIP = { s0, xi, wsp + (size_t)(l * 3 + 0) * WSZ, b0, nullptr, ipA,  n_ip,  nbIP,  1 };
        combine_fused_kernel<<<nbCON + nbIP, 512, DSMEM_BYTES>>>(cC1, cIP);

        CombSeg cC2 = { s2, xc, wsp + (size_t)(l * 3 + 2) * WSZ, b2, tmpC, conA, n_con, nbCON, 2 };
        CombSeg cNil = {};
        combine_fused_kernel<<<nbCON, 512, DSMEM_BYTES>>>(cC2, cNil);

        // ---------- spatial aggregation (2 segments, fused) ----------
        AggSeg a3 = { ipA,  off3, ei3, s1, n_con };
        AggSeg a4 = { conA, off4, ei4, s0, n_ip };
        agg_fused_kernel<<<dim3(aggBlocksCon, 2), 256>>>(a3, a4, a4);

        // ---------- spatial combines fused ----------
        float* out_ip  = (l == 1) ? out : ipB;
        float* out_con = (l == 1) ? (out + (size_t)n_ip * H) : conB;

        CombSeg cSC = { s1, conA, wsp + (size_t)(6 + l * 2 + 0) * WSZ, bs0, nullptr, out_con, n_con, nbCON, 1 };
        CombSeg cSI = { s0, ipA,  wsp + (size_t)(6 + l * 2 + 1) * WSZ, bs1, nullptr, out_ip,  n_ip,  nbIP,  1 };
        combine_fused_kernel<<<nbCON + nbIP, 512, DSMEM_BYTES>>>(cSC, cSI);
    }
}

// round 12
// speedup vs baseline: 1.4131x; 1.1139x over previous
#include <cuda_runtime.h>
#include <cuda_fp16.h>
#include <math.h>
#include <stdint.h>

#define H 128
#define N_IP_MAX 50000
#define N_CON_MAX 200000
#define MAXB 256

// ---------------- scratch ----------------
__device__ float g_s0[N_IP_MAX * H];
__device__ float g_s1[N_CON_MAX * H];
__device__ float g_s2[N_CON_MAX * H];
__device__ float g_tmpC[N_CON_MAX * H];
__device__ float g_ipA[N_IP_MAX * H];
__device__ float g_ipB[N_IP_MAX * H];
__device__ float g_conA[N_CON_MAX * H];
__device__ float g_conB[N_CON_MAX * H];
__device__ uint32_t g_wsplit[10 * 16384];   // per sage: [k-pair][col] fp16x2
__device__ int g_cnt[700032];               // .bss zero; fill counts it back down to zero
__device__ int g_off[700064];
__device__ int g_eidx[1800064];
__device__ int g_part[5 * MAXB];

struct EdgeDesc { const int* src; const int* dst; int nE; int n_dst; int dstbase; int ebase; };
struct BuildParams { EdgeDesc e[5]; };
struct AggSeg { const float* x; const int* off; const int* eidx; float* s; int n; };
struct CombSeg {
    const float* s; const float* xdst; const uint32_t* w; const float* bb;
    const float* addin; float* out; int n; int nblk; int mode;  // 0 norm,1 +lrelu,2 +addin+lrelu
};

// ---------------- helpers ----------------
__device__ __forceinline__ uint32_t packh2(float x0, float x1)
{
    uint32_t r;
    asm("cvt.rn.f16x2.f32 %0, %1, %2;" : "=r"(r) : "f"(x1), "f"(x0));
    return r;
}

__device__ __forceinline__ void mma16816h(float* d, const uint32_t* a, uint32_t b0, uint32_t b1)
{
    asm volatile(
        "mma.sync.aligned.m16n8k16.row.col.f32.f16.f16.f32 "
        "{%0,%1,%2,%3}, {%4,%5,%6,%7}, {%8,%9}, {%0,%1,%2,%3};"
        : "+f"(d[0]), "+f"(d[1]), "+f"(d[2]), "+f"(d[3])
        : "r"(a[0]), "r"(a[1]), "r"(a[2]), "r"(a[3]), "r"(b0), "r"(b1));
}

__device__ __forceinline__ void cp_async16(uint32_t smem_dst, const void* gsrc)
{
    asm volatile("cp.async.ca.shared.global [%0], [%1], 16;" :: "r"(smem_dst), "l"(gsrc));
}
__device__ __forceinline__ void cp_commit() { asm volatile("cp.async.commit_group;"); }
__device__ __forceinline__ void cp_wait0()  { asm volatile("cp.async.wait_group 0;" ::: "memory"); }

__device__ __forceinline__ int permq(int p) { return (p < 4) ? (2 * p) : (2 * (p - 4) + 1); }

// ---------------- fused presplit (single fp16 W) + degree count ----------------
__global__ void precount_kernel(const float* __restrict__ Wl_t, const float* __restrict__ Wr_t,
                                const float* __restrict__ Wl_s, const float* __restrict__ Wr_s,
                                uint32_t* __restrict__ out, BuildParams bp,
                                int* __restrict__ cnt, int cntBlocks)
{
    int bx = blockIdx.x;
    if (bx < 640) {
        int sg  = bx >> 6;
        int idx = (bx & 63) * 256 + threadIdx.x;
        int p = idx >> 7;
        int col = idx & 127;
        const float *Wl, *Wr;
        if (sg < 6) { Wl = Wl_t + (size_t)sg * H * H;       Wr = Wr_t + (size_t)sg * H * H; }
        else        { Wl = Wl_s + (size_t)(sg - 6) * H * H; Wr = Wr_s + (size_t)(sg - 6) * H * H; }
        int k0 = 2 * p;
        float x0 = (k0 < H)     ? Wl[k0 * H + col]       : Wr[(k0 - H) * H + col];
        float x1 = (k0 + 1 < H) ? Wl[(k0 + 1) * H + col] : Wr[(k0 + 1 - H) * H + col];
        out[(size_t)sg * 16384 + idx] = packh2(x0, x1);
    } else {
        int b2 = bx - 640;
        int t = b2 / cntBlocks;
        int i = (b2 % cntBlocks) * 256 + threadIdx.x;
        EdgeDesc d = bp.e[t];
        if (i < d.nE) atomicAdd(&cnt[d.dstbase + d.dst[i]], 1);
    }
}

// ---------------- CSR scans ----------------
__global__ void scan_phase1(BuildParams bp, const int* __restrict__ cnt,
                            int* __restrict__ off, int* __restrict__ part)
{
    int t = blockIdx.y;
    EdgeDesc d = bp.e[t];
    int L = d.n_dst;
    int i = blockIdx.x * 1024 + threadIdx.x;
    __shared__ int sh[1024];
    int v = (i < L) ? cnt[d.dstbase + i] : 0;
    sh[threadIdx.x] = v;
    __syncthreads();
    for (int o = 1; o < 1024; o <<= 1) {
        int x = (threadIdx.x >= o) ? sh[threadIdx.x - o] : 0;
        __syncthreads();
        sh[threadIdx.x] += x;
        __syncthreads();
    }
    if (i < L) off[d.dstbase + t + i] = sh[threadIdx.x] - v;
    if (threadIdx.x == 1023) part[t * MAXB + blockIdx.x] = sh[1023];
}

__global__ void scan_phase23(BuildParams bp, int* __restrict__ off, const int* __restrict__ part)
{
    int t = blockIdx.y;
    EdgeDesc d = bp.e[t];
    int L = d.n_dst;
    __shared__ int pref[MAXB];
    if (threadIdx.x < MAXB) pref[threadIdx.x] = part[t * MAXB + threadIdx.x];
    __syncthreads();
    for (int o = 1; o < MAXB; o <<= 1) {
        int x = 0;
        if (threadIdx.x < MAXB && threadIdx.x >= o) x = pref[threadIdx.x - o];
        __syncthreads();
        if (threadIdx.x < MAXB) pref[threadIdx.x] += x;
        __syncthreads();
    }
    int add = (blockIdx.x == 0) ? 0 : pref[blockIdx.x - 1];
    int i = blockIdx.x * 1024 + threadIdx.x;
    if (i < L) off[d.dstbase + t + i] += add;
    if (blockIdx.x == 0 && threadIdx.x == 0) off[d.dstbase + t + L] = d.nE;
}

__global__ void fill_kernel(BuildParams bp, int* __restrict__ cnt,
                            const int* __restrict__ off, int* __restrict__ eidx)
{
    int t = blockIdx.y;
    EdgeDesc d = bp.e[t];
    int i = blockIdx.x * blockDim.x + threadIdx.x;
    if (i >= d.nE) return;
    int dd = d.dst[i];
    int pos = off[d.dstbase + t + dd] + atomicAdd(&cnt[d.dstbase + dd], -1) - 1;
    eidx[d.ebase + pos] = d.src[i];
}

// ---------------- fused CSR mean-aggregation (up to 3 segments) ----------------
__global__ void agg_fused_kernel(AggSeg a0, AggSeg a1, AggSeg a2)
{
    AggSeg sg;
    if (blockIdx.y == 0) sg = a0;
    else if (blockIdx.y == 1) sg = a1;
    else sg = a2;
    int w = (blockIdx.x * blockDim.x + threadIdx.x) >> 5;
    int lane = threadIdx.x & 31;
    if (w >= sg.n) return;
    int start = sg.off[w], end = sg.off[w + 1];
    float4 acc = make_float4(0.f, 0.f, 0.f, 0.f);
    for (int e = start; e < end; e++) {
        int si = __ldg(sg.eidx + e);
        float4 v = reinterpret_cast<const float4*>(sg.x)[(size_t)si * 32 + lane];
        acc.x += v.x; acc.y += v.y; acc.z += v.z; acc.w += v.w;
    }
    float inv = 1.0f / (float)max(end - start, 1);
    acc.x *= inv; acc.y *= inv; acc.z *= inv; acc.w *= inv;
    reinterpret_cast<float4*>(sg.s)[(size_t)w * 32 + lane] = acc;
}

// ---------------- fused SAGE combine (single fp16 MMA per fragment) ----------------
// A smem: [256 rows][8 slots u32 fp16x2, permuted], stride 8.
// W smem: [128 pair-rows][128 cols u32 fp16x2], stride 132 (conflict-free: bank = 4c+g).
#define ASTRIDE 8
#define WSTRIDE 132
#define DSMEM_BYTES ((2 * 256 * ASTRIDE + 128 * WSTRIDE) * 4)

__global__ void __launch_bounds__(512) combine_fused_kernel(CombSeg A, CombSeg B)
{
    extern __shared__ uint32_t dyn[];
    uint32_t* Asm0 = dyn;
    uint32_t* Asm1 = dyn + 256 * ASTRIDE;
    uint32_t* Wsm  = dyn + 2 * 256 * ASTRIDE;
    __shared__ float ssred[256];

    CombSeg cs;
    int blk = blockIdx.x;
    if (blk < A.nblk) cs = A;
    else { blk -= A.nblk; cs = B; }

    const int tid  = threadIdx.x;
    const int row0 = blk * 256;
    const int n    = cs.n;
    const int mode = cs.mode;

    // one-shot W stage: 4096 x 16B chunks (64KB)
    {
        uint32_t wb = (uint32_t)__cvta_generic_to_shared(Wsm);
#pragma unroll
        for (int it = 0; it < 8; it++) {
            int ch = tid + it * 512;
            int p = ch >> 5, o = ch & 31;
            cp_async16(wb + (uint32_t)(p * WSTRIDE + o * 4) * 4, cs.w + p * 128 + o * 4);
        }
        cp_commit();
    }
    if (tid < 256) ssred[tid] = 0.0f;

    // ---- A producer mapping ----
    const int ar   = tid >> 1;
    const int half = tid & 1;
    const int grow = row0 + ar;
    const bool rowok = grow < n;

    float af[8];
    auto load_a = [&](int kt) {
        int k0 = kt * 16 + half * 8;
        const float* ap = (k0 < H) ? (cs.s + (size_t)grow * H + k0)
                                   : (cs.xdst + (size_t)grow * H + (k0 - H));
        float4 f0 = make_float4(0.f, 0.f, 0.f, 0.f), f1 = f0;
        if (rowok) {
            f0 = *reinterpret_cast<const float4*>(ap);
            f1 = *reinterpret_cast<const float4*>(ap + 4);
        }
        af[0] = f0.x; af[1] = f0.y; af[2] = f0.z; af[3] = f0.w;
        af[4] = f1.x; af[5] = f1.y; af[6] = f1.z; af[7] = f1.w;
    };

    auto store_a = [&](uint32_t* buf) {
#pragma unroll
        for (int j = 0; j < 4; j++) {
            int p = half * 4 + j;
            buf[ar * ASTRIDE + permq(p)] = packh2(af[2 * j], af[2 * j + 1]);
        }
    };

    // ---- mma mapping ----
    const int lane = tid & 31;
    const int wid  = tid >> 5;
    const int wm   = wid >> 2;
    const int wn   = wid & 3;
    const int g    = lane >> 2;
    const int c    = lane & 3;

    float acc[4][4][4];
#pragma unroll
    for (int mt = 0; mt < 4; mt++)
#pragma unroll
        for (int nt = 0; nt < 4; nt++)
#pragma unroll
            for (int j = 0; j < 4; j++) acc[mt][nt][j] = 0.0f;

    load_a(0);
    store_a(Asm0);
    cp_wait0();
    __syncthreads();

    for (int kt = 0; kt < 16; kt++) {
        uint32_t* cur = (kt & 1) ? Asm1 : Asm0;
        uint32_t* nxt = (kt & 1) ? Asm0 : Asm1;
        if (kt < 15) load_a(kt + 1);

        uint32_t ahf[4][4];
#pragma unroll
        for (int mt = 0; mt < 4; mt++) {
            int R = wm * 64 + mt * 16;
            uint2 v0 = *reinterpret_cast<const uint2*>(&cur[(R + g) * ASTRIDE + c * 2]);
            uint2 v1 = *reinterpret_cast<const uint2*>(&cur[(R + g + 8) * ASTRIDE + c * 2]);
            ahf[mt][0] = v0.x; ahf[mt][1] = v1.x; ahf[mt][2] = v0.y; ahf[mt][3] = v1.y;
        }
#pragma unroll
        for (int nt = 0; nt < 4; nt++) {
            int col = wn * 32 + nt * 8 + g;
            uint32_t w0 = Wsm[(kt * 8 + c) * WSTRIDE + col];
            uint32_t w1 = Wsm[(kt * 8 + c + 4) * WSTRIDE + col];
#pragma unroll
            for (int mt = 0; mt < 4; mt++)
                mma16816h(acc[mt][nt], ahf[mt], w0, w1);
        }

        if (kt < 15) store_a(nxt);
        __syncthreads();
    }

    // ---- epilogue ----
#pragma unroll
    for (int mt = 0; mt < 4; mt++) {
        float ss0 = 0.0f, ss1 = 0.0f;
#pragma unroll
        for (int nt = 0; nt < 4; nt++) {
            int col = wn * 32 + nt * 8 + c * 2;
            float b0v = __ldg(cs.bb + col), b1v = __ldg(cs.bb + col + 1);
            acc[mt][nt][0] += b0v; acc[mt][nt][1] += b1v;
            acc[mt][nt][2] += b0v; acc[mt][nt][3] += b1v;
            ss0 += acc[mt][nt][0] * acc[mt][nt][0] + acc[mt][nt][1] * acc[mt][nt][1];
            ss1 += acc[mt][nt][2] * acc[mt][nt][2] + acc[mt][nt][3] * acc[mt][nt][3];
        }
        ss0 += __shfl_xor_sync(0xffffffffu, ss0, 1);
        ss0 += __shfl_xor_sync(0xffffffffu, ss0, 2);
        ss1 += __shfl_xor_sync(0xffffffffu, ss1, 1);
        ss1 += __shfl_xor_sync(0xffffffffu, ss1, 2);
        if (c == 0) {
            atomicAdd(&ssred[wm * 64 + mt * 16 + g],     ss0);
            atomicAdd(&ssred[wm * 64 + mt * 16 + 8 + g], ss1);
        }
    }
    __syncthreads();

#pragma unroll
    for (int mt = 0; mt < 4; mt++) {
        int rl0 = wm * 64 + mt * 16 + g;
        int rl1 = rl0 + 8;
        float inv0 = 1.0f / fmaxf(sqrtf(ssred[rl0]), 1e-12f);
        float inv1 = 1.0f / fmaxf(sqrtf(ssred[rl1]), 1e-12f);
        int gr0 = row0 + rl0;
        int gr1 = row0 + rl1;
#pragma unroll
        for (int nt = 0; nt < 4; nt++) {
            int col = wn * 32 + nt * 8 + c * 2;
            if (gr0 < n) {
                float v0 = acc[mt][nt][0] * inv0;
                float v1 = acc[mt][nt][1] * inv0;
                if (mode == 2) {
                    float2 a2 = *reinterpret_cast<const float2*>(cs.addin + (size_t)gr0 * H + col);
                    v0 += a2.x; v1 += a2.y;
                }
                if (mode >= 1) {
                    v0 = (v0 >= 0.f) ? v0 : 0.01f * v0;
                    v1 = (v1 >= 0.f) ? v1 : 0.01f * v1;
                }
                *reinterpret_cast<float2*>(cs.out + (size_t)gr0 * H + col) = make_float2(v0, v1);
            }
            if (gr1 < n) {
                float v2 = acc[mt][nt][2] * inv1;
                float v3 = acc[mt][nt][3] * inv1;
                if (mode == 2) {
                    float2 a2 = *reinterpret_cast<const float2*>(cs.addin + (size_t)gr1 * H + col);
                    v2 += a2.x; v3 += a2.y;
                }
                if (mode >= 1) {
                    v2 = (v2 >= 0.f) ? v2 : 0.01f * v2;
                    v3 = (v3 >= 0.f) ? v3 : 0.01f * v3;
                }
                *reinterpret_cast<float2*>(cs.out + (size_t)gr1 * H + col) = make_float2(v2, v3);
            }
        }
    }
}

// ---------------- host ----------------
extern "C" void kernel_launch(void* const* d_in, const int* in_sizes, int n_in,
                              void* d_out, int out_size)
{
    const float* x_ip  = (const float*)d_in[0];
    const float* x_con = (const float*)d_in[1];
    const int* src_ipcon = (const int*)d_in[2];
    const int* dst_ipcon = (const int*)d_in[3];
    const int* src_conip = (const int*)d_in[4];
    const int* dst_conip = (const int*)d_in[5];
    const int* src_ipip  = (const int*)d_in[6];
    const int* dst_ipip  = (const int*)d_in[7];
    const int* src_csrc  = (const int*)d_in[8];
    const int* dst_csrc  = (const int*)d_in[9];
    const int* src_cdst  = (const int*)d_in[10];
    const int* dst_cdst  = (const int*)d_in[11];
    const float* Wl_t = (const float*)d_in[12];
    const float* bl_t = (const float*)d_in[13];
    const float* Wr_t = (const float*)d_in[14];
    const float* Wl_s = (const float*)d_in[15];
    const float* bl_s = (const float*)d_in[16];
    const float* Wr_s = (const float*)d_in[17];

    const int n_ip  = in_sizes[0] / H;
    const int n_con = in_sizes[1] / H;
    const int nE_ipcon = in_sizes[2];
    const int nE_conip = in_sizes[4];
    const int nE_ipip  = in_sizes[6];
    const int nE_csrc  = in_sizes[8];
    const int nE_cdst  = in_sizes[10];

    float *s0, *s1, *s2, *tmpC, *ipA, *ipB, *conA, *conB;
    uint32_t* wsp;
    int *cnt, *off, *eidx, *part;
    cudaGetSymbolAddress((void**)&s0,   g_s0);
    cudaGetSymbolAddress((void**)&s1,   g_s1);
    cudaGetSymbolAddress((void**)&s2,   g_s2);
    cudaGetSymbolAddress((void**)&tmpC, g_tmpC);
    cudaGetSymbolAddress((void**)&ipA,  g_ipA);
    cudaGetSymbolAddress((void**)&ipB,  g_ipB);
    cudaGetSymbolAddress((void**)&conA, g_conA);
    cudaGetSymbolAddress((void**)&conB, g_conB);
    cudaGetSymbolAddress((void**)&wsp,  g_wsplit);
    cudaGetSymbolAddress((void**)&cnt,  g_cnt);
    cudaGetSymbolAddress((void**)&off,  g_off);
    cudaGetSymbolAddress((void**)&eidx, g_eidx);
    cudaGetSymbolAddress((void**)&part, g_part);

    cudaFuncSetAttribute(combine_fused_kernel, cudaFuncAttributeMaxDynamicSharedMemorySize, DSMEM_BYTES);

    float* out = (float*)d_out;

    BuildParams bp;
    bp.e[0] = { src_ipip,  dst_ipip,  nE_ipip,  n_ip,  0,                0 };
    bp.e[1] = { src_csrc,  dst_csrc,  nE_csrc,  n_con, n_ip,             nE_ipip };
    bp.e[2] = { src_cdst,  dst_cdst,  nE_cdst,  n_con, n_ip + n_con,     nE_ipip + nE_csrc };
    bp.e[3] = { src_ipcon, dst_ipcon, nE_ipcon, n_con, n_ip + 2 * n_con, nE_ipip + nE_csrc + nE_cdst };
    bp.e[4] = { src_conip, dst_conip, nE_conip, n_ip,  n_ip + 3 * n_con, nE_ipip + nE_csrc + nE_cdst + nE_ipcon };

    int maxE = nE_ipip;
    if (nE_csrc  > maxE) maxE = nE_csrc;
    if (nE_cdst  > maxE) maxE = nE_cdst;
    if (nE_ipcon > maxE) maxE = nE_ipcon;
    if (nE_conip > maxE) maxE = nE_conip;
    const int cntBlocks = (maxE + 255) / 256;

    precount_kernel<<<640 + 5 * cntBlocks, 256>>>(Wl_t, Wr_t, Wl_s, Wr_s, wsp, bp, cnt, cntBlocks);
    scan_phase1<<<dim3(MAXB, 5), 1024>>>(bp, cnt, off, part);
    scan_phase23<<<dim3(MAXB, 5), 1024>>>(bp, off, part);
    fill_kernel<<<dim3(cntBlocks, 5), 256>>>(bp, cnt, off, eidx);

    const int* off0 = off + bp.e[0].dstbase + 0;
    const int* off1 = off + bp.e[1].dstbase + 1;
    const int* off2 = off + bp.e[2].dstbase + 2;
    const int* off3 = off + bp.e[3].dstbase + 3;
    const int* off4 = off + bp.e[4].dstbase + 4;
    const int* ei0 = eidx + bp.e[0].ebase;
    const int* ei1 = eidx + bp.e[1].ebase;
    const int* ei2 = eidx + bp.e[2].ebase;
    const int* ei3 = eidx + bp.e[3].ebase;
    const int* ei4 = eidx + bp.e[4].ebase;

    const int nbIP  = (n_ip  + 255) / 256;
    const int nbCON = (n_con + 255) / 256;
    const int aggBlocksCon = (n_con * 32 + 255) / 256;
    const size_t WSZ = 16384;

    for (int l = 0; l < 2; l++) {
        const float* xi = (l == 0) ? x_ip  : ipB;
        const float* xc = (l == 0) ? x_con : conB;

        const float* b0 = bl_t + (size_t)(l * 3 + 0) * H;
        const float* b1 = bl_t + (size_t)(l * 3 + 1) * H;
        const float* b2 = bl_t + (size_t)(l * 3 + 2) * H;
        const float* bs0 = bl_s + (size_t)(l * 2 + 0) * H;
        const float* bs1 = bl_s + (size_t)(l * 2 + 1) * H;

        // ---------- temporal aggregation (3 segments, fused) ----------
        AggSeg a0 = { xi, off0, ei0, s0, n_ip };
        AggSeg a1 = { xc, off1, ei1, s1, n_con };
        AggSeg a2 = { xc, off2, ei2, s2, n_con };
        agg_fused_kernel<<<dim3(aggBlocksCon, 3), 256>>>(a0, a1, a2);

        // ---------- temporal combines: (con sage1 + ip sage) fused, then con sage2 ----------
        CombSeg cC1 = { s1, xc, wsp + (size_t)(l * 3 + 1) * WSZ, b1, nullptr, tmpC, n_con, nbCON, 0 };
        CombSeg cIP = { s0, xi, wsp + (size_t)(l * 3 + 0) * WSZ, b0, nullptr, ipA,  n_ip,  nbIP,  1 };
        combine_fused_kernel<<<nbCON + nbIP, 512, DSMEM_BYTES>>>(cC1, cIP);

        CombSeg cC2 = { s2, xc, wsp + (size_t)(l * 3 + 2) * WSZ, b2, tmpC, conA, n_con, nbCON, 2 };
        CombSeg cNil = {};
        combine_fused_kernel<<<nbCON, 512, DSMEM_BYTES>>>(cC2, cNil);

        // ---------- spatial aggregation (2 segments, fused) ----------
        AggSeg a3 = { ipA,  off3, ei3, s1, n_con };
        AggSeg a4 = { conA, off4, ei4, s0, n_ip };
        agg_fused_kernel<<<dim3(aggBlocksCon, 2), 256>>>(a3, a4, a4);

        // ---------- spatial combines fused ----------
        float* out_ip  = (l == 1) ? out : ipB;
        float* out_con = (l == 1) ? (out + (size_t)n_ip * H) : conB;

        CombSeg cSC = { s1, conA, wsp + (size_t)(6 + l * 2 + 0) * WSZ, bs0, nullptr, out_con, n_con, nbCON, 1 };
        CombSeg cSI = { s0, ipA,  wsp + (size_t)(6 + l * 2 + 1) * WSZ, bs1, nullptr, out_ip,  n_ip,  nbIP,  1 };
        combine_fused_kernel<<<nbCON + nbIP, 512, DSMEM_BYTES>>>(cSC, cSI);
    }
}

// round 13
// speedup vs baseline: 1.7212x; 1.2180x over previous
#include <cuda_runtime.h>
#include <cuda_fp16.h>
#include <math.h>
#include <stdint.h>

#define H 128
#define N_IP_MAX 50000
#define N_CON_MAX 200000
#define MAXB 256

// ---------------- scratch ----------------
// s buffers: agg output, fp16x2, combine-ready layout: [row][kstep 0..7][slot 0..7]
// (64 u32 = 256B per row). Padded +256 rows so tail-CTA cp.async stays in bounds.
__device__ uint32_t g_s0[(N_IP_MAX + 256) * 64];
__device__ uint32_t g_s1[(N_CON_MAX + 256) * 64];
__device__ uint32_t g_s2[(N_CON_MAX + 256) * 64];
__device__ float g_tmpC[N_CON_MAX * H];
__device__ float g_ipA[N_IP_MAX * H];
__device__ float g_ipB[N_IP_MAX * H];
__device__ float g_conA[N_CON_MAX * H];
__device__ float g_conB[N_CON_MAX * H];
__device__ uint32_t g_wsplit[10 * 16384];   // per sage: [k-pair][col] fp16x2
__device__ int g_cnt[700032];               // .bss zero; fill counts it back down to zero
__device__ int g_off[700064];
__device__ int g_eidx[1800064];
__device__ int g_part[5 * MAXB];

struct EdgeDesc { const int* src; const int* dst; int nE; int n_dst; int dstbase; int ebase; };
struct BuildParams { EdgeDesc e[5]; };
struct AggSeg { const float* x; const int* off; const int* eidx; uint32_t* s; int n; };
struct CombSeg {
    const uint32_t* s;   // fp16 permuted agg output
    const float* xdst; const uint32_t* w; const float* bb;
    const float* addin; float* out; int n; int nblk; int mode;  // 0 norm,1 +lrelu,2 +addin+lrelu
};

// ---------------- helpers ----------------
__device__ __forceinline__ uint32_t packh2(float x0, float x1)
{
    uint32_t r;
    asm("cvt.rn.f16x2.f32 %0, %1, %2;" : "=r"(r) : "f"(x1), "f"(x0));
    return r;
}

__device__ __forceinline__ void mma16816h(float* d, const uint32_t* a, uint32_t b0, uint32_t b1)
{
    asm volatile(
        "mma.sync.aligned.m16n8k16.row.col.f32.f16.f16.f32 "
        "{%0,%1,%2,%3}, {%4,%5,%6,%7}, {%8,%9}, {%0,%1,%2,%3};"
        : "+f"(d[0]), "+f"(d[1]), "+f"(d[2]), "+f"(d[3])
        : "r"(a[0]), "r"(a[1]), "r"(a[2]), "r"(a[3]), "r"(b0), "r"(b1));
}

__device__ __forceinline__ void cp_async16(uint32_t smem_dst, const void* gsrc)
{
    asm volatile("cp.async.ca.shared.global [%0], [%1], 16;" :: "r"(smem_dst), "l"(gsrc));
}
__device__ __forceinline__ void cp_commit() { asm volatile("cp.async.commit_group;"); }
__device__ __forceinline__ void cp_wait0()  { asm volatile("cp.async.wait_group 0;" ::: "memory"); }

__device__ __forceinline__ int permq(int p) { return (p < 4) ? (2 * p) : (2 * (p - 4) + 1); }

// ---------------- fused presplit (single fp16 W) + degree count ----------------
__global__ void precount_kernel(const float* __restrict__ Wl_t, const float* __restrict__ Wr_t,
                                const float* __restrict__ Wl_s, const float* __restrict__ Wr_s,
                                uint32_t* __restrict__ out, BuildParams bp,
                                int* __restrict__ cnt, int cntBlocks)
{
    int bx = blockIdx.x;
    if (bx < 640) {
        int sg  = bx >> 6;
        int idx = (bx & 63) * 256 + threadIdx.x;
        int p = idx >> 7;
        int col = idx & 127;
        const float *Wl, *Wr;
        if (sg < 6) { Wl = Wl_t + (size_t)sg * H * H;       Wr = Wr_t + (size_t)sg * H * H; }
        else        { Wl = Wl_s + (size_t)(sg - 6) * H * H; Wr = Wr_s + (size_t)(sg - 6) * H * H; }
        int k0 = 2 * p;
        float x0 = (k0 < H)     ? Wl[k0 * H + col]       : Wr[(k0 - H) * H + col];
        float x1 = (k0 + 1 < H) ? Wl[(k0 + 1) * H + col] : Wr[(k0 + 1 - H) * H + col];
        out[(size_t)sg * 16384 + idx] = packh2(x0, x1);
    } else {
        int b2 = bx - 640;
        int t = b2 / cntBlocks;
        int i = (b2 % cntBlocks) * 256 + threadIdx.x;
        EdgeDesc d = bp.e[t];
        if (i < d.nE) atomicAdd(&cnt[d.dstbase + d.dst[i]], 1);
    }
}

// ---------------- CSR scans ----------------
__global__ void scan_phase1(BuildParams bp, const int* __restrict__ cnt,
                            int* __restrict__ off, int* __restrict__ part)
{
    int t = blockIdx.y;
    EdgeDesc d = bp.e[t];
    int L = d.n_dst;
    int i = blockIdx.x * 1024 + threadIdx.x;
    __shared__ int sh[1024];
    int v = (i < L) ? cnt[d.dstbase + i] : 0;
    sh[threadIdx.x] = v;
    __syncthreads();
    for (int o = 1; o < 1024; o <<= 1) {
        int x = (threadIdx.x >= o) ? sh[threadIdx.x - o] : 0;
        __syncthreads();
        sh[threadIdx.x] += x;
        __syncthreads();
    }
    if (i < L) off[d.dstbase + t + i] = sh[threadIdx.x] - v;
    if (threadIdx.x == 1023) part[t * MAXB + blockIdx.x] = sh[1023];
}

__global__ void scan_phase23(BuildParams bp, int* __restrict__ off, const int* __restrict__ part)
{
    int t = blockIdx.y;
    EdgeDesc d = bp.e[t];
    int L = d.n_dst;
    __shared__ int pref[MAXB];
    if (threadIdx.x < MAXB) pref[threadIdx.x] = part[t * MAXB + threadIdx.x];
    __syncthreads();
    for (int o = 1; o < MAXB; o <<= 1) {
        int x = 0;
        if (threadIdx.x < MAXB && threadIdx.x >= o) x = pref[threadIdx.x - o];
        __syncthreads();
        if (threadIdx.x < MAXB) pref[threadIdx.x] += x;
        __syncthreads();
    }
    int add = (blockIdx.x == 0) ? 0 : pref[blockIdx.x - 1];
    int i = blockIdx.x * 1024 + threadIdx.x;
    if (i < L) off[d.dstbase + t + i] += add;
    if (blockIdx.x == 0 && threadIdx.x == 0) off[d.dstbase + t + L] = d.nE;
}

__global__ void fill_kernel(BuildParams bp, int* __restrict__ cnt,
                            const int* __restrict__ off, int* __restrict__ eidx)
{
    int t = blockIdx.y;
    EdgeDesc d = bp.e[t];
    int i = blockIdx.x * blockDim.x + threadIdx.x;
    if (i >= d.nE) return;
    int dd = d.dst[i];
    int pos = off[d.dstbase + t + dd] + atomicAdd(&cnt[d.dstbase + dd], -1) - 1;
    eidx[d.ebase + pos] = d.src[i];
}

// ---------------- fused CSR mean-aggregation, fp16 combine-ready output ----------------
// warp per dst row; lane covers k = 4*lane..4*lane+3 (pairs 2*lane, 2*lane+1)
__global__ void agg_fused_kernel(AggSeg a0, AggSeg a1, AggSeg a2)
{
    AggSeg sg;
    if (blockIdx.y == 0) sg = a0;
    else if (blockIdx.y == 1) sg = a1;
    else sg = a2;
    int w = (blockIdx.x * blockDim.x + threadIdx.x) >> 5;
    int lane = threadIdx.x & 31;
    if (w >= sg.n) return;
    int start = sg.off[w], end = sg.off[w + 1];
    float4 acc = make_float4(0.f, 0.f, 0.f, 0.f);
    for (int e = start; e < end; e++) {
        int si = __ldg(sg.eidx + e);
        float4 v = reinterpret_cast<const float4*>(sg.x)[(size_t)si * 32 + lane];
        acc.x += v.x; acc.y += v.y; acc.z += v.z; acc.w += v.w;
    }
    float inv = 1.0f / (float)max(end - start, 1);
    // pack to fp16 pairs in combine layout: [row][kstep=lane>>2][slot perm]
    uint32_t v0 = packh2(acc.x * inv, acc.y * inv);
    uint32_t v1 = packh2(acc.z * inv, acc.w * inv);
    int p0 = (2 * lane) & 7;
    uint32_t* base = sg.s + (size_t)w * 64 + (lane >> 2) * 8;
    base[permq(p0)]     = v0;
    base[permq(p0 + 1)] = v1;
}

// ---------------- fused SAGE combine: fully-resident A, barrier-free MMA loop ------
// A smem: 16 ksteps x [256 rows][8 slots u32] = 128KB. W smem: 128x132 u32 = 66KB.
#define WSTRIDE 132
#define DSMEM_BYTES ((16 * 2048 + 128 * WSTRIDE) * 4)

__global__ void __launch_bounds__(512) combine_fused_kernel(CombSeg A, CombSeg B)
{
    extern __shared__ uint32_t dyn[];
    uint32_t* Asm = dyn;                 // [kt][row*8+slot]
    uint32_t* Wsm = dyn + 16 * 2048;
    __shared__ float ssred[256];

    CombSeg cs;
    int blk = blockIdx.x;
    if (blk < A.nblk) cs = A;
    else { blk -= A.nblk; cs = B; }

    const int tid  = threadIdx.x;
    const int row0 = blk * 256;
    const int n    = cs.n;
    const int mode = cs.mode;

    const uint32_t ab = (uint32_t)__cvta_generic_to_shared(Asm);
    const uint32_t wb = (uint32_t)__cvta_generic_to_shared(Wsm);

    // ---- stage W (66KB) ----
#pragma unroll
    for (int it = 0; it < 8; it++) {
        int ch = tid + it * 512;
        int p = ch >> 5, o = ch & 31;
        cp_async16(wb + (uint32_t)(p * WSTRIDE + o * 4) * 4, cs.w + p * 128 + o * 4);
    }
    // ---- stage s-half (ksteps 0..7, 64KB) straight from fp16 agg output ----
    {
        int row = tid >> 1, hf = tid & 1;
        const uint32_t* srow = cs.s + (size_t)(row0 + row) * 64 + hf * 4;
#pragma unroll
        for (int kt = 0; kt < 8; kt++)
            cp_async16(ab + (uint32_t)(kt * 2048 + row * 8 + hf * 4) * 4, srow + kt * 8);
    }
    cp_commit();

    if (tid < 256) ssred[tid] = 0.0f;

    // ---- convert xdst-half (ksteps 8..15) into smem while cp.async flies ----
    {
        const int ar   = tid >> 1;
        const int half = tid & 1;
        const int grow = row0 + ar;
        const bool rowok = grow < n;
#pragma unroll
        for (int kt8 = 0; kt8 < 8; kt8++) {
            int k0 = kt8 * 16 + half * 8;
            float4 f0 = make_float4(0.f, 0.f, 0.f, 0.f), f1 = f0;
            if (rowok) {
                const float* ap = cs.xdst + (size_t)grow * H + k0;
                f0 = *reinterpret_cast<const float4*>(ap);
                f1 = *reinterpret_cast<const float4*>(ap + 4);
            }
            uint32_t* dst = Asm + (8 + kt8) * 2048 + ar * 8;
            dst[permq(half * 4 + 0)] = packh2(f0.x, f0.y);
            dst[permq(half * 4 + 1)] = packh2(f0.z, f0.w);
            dst[permq(half * 4 + 2)] = packh2(f1.x, f1.y);
            dst[permq(half * 4 + 3)] = packh2(f1.z, f1.w);
        }
    }

    cp_wait0();
    __syncthreads();

    // ---- mma mapping ----
    const int lane = tid & 31;
    const int wid  = tid >> 5;
    const int wm   = wid >> 2;
    const int wn   = wid & 3;
    const int g    = lane >> 2;
    const int c    = lane & 3;

    float acc[4][4][4];
#pragma unroll
    for (int mt = 0; mt < 4; mt++)
#pragma unroll
        for (int nt = 0; nt < 4; nt++)
#pragma unroll
            for (int j = 0; j < 4; j++) acc[mt][nt][j] = 0.0f;

    // ---- barrier-free MMA loop over 16 resident k-steps ----
#pragma unroll 4
    for (int kt = 0; kt < 16; kt++) {
        const uint32_t* cur = Asm + kt * 2048;
        uint32_t ahf[4][4];
#pragma unroll
        for (int mt = 0; mt < 4; mt++) {
            int R = wm * 64 + mt * 16;
            uint2 v0 = *reinterpret_cast<const uint2*>(&cur[(R + g) * 8 + c * 2]);
            uint2 v1 = *reinterpret_cast<const uint2*>(&cur[(R + g + 8) * 8 + c * 2]);
            ahf[mt][0] = v0.x; ahf[mt][1] = v1.x; ahf[mt][2] = v0.y; ahf[mt][3] = v1.y;
        }
#pragma unroll
        for (int nt = 0; nt < 4; nt++) {
            int col = wn * 32 + nt * 8 + g;
            uint32_t w0 = Wsm[(kt * 8 + c) * WSTRIDE + col];
            uint32_t w1 = Wsm[(kt * 8 + c + 4) * WSTRIDE + col];
#pragma unroll
            for (int mt = 0; mt < 4; mt++)
                mma16816h(acc[mt][nt], ahf[mt], w0, w1);
        }
    }

    // ---- epilogue ----
#pragma unroll
    for (int mt = 0; mt < 4; mt++) {
        float ss0 = 0.0f, ss1 = 0.0f;
#pragma unroll
        for (int nt = 0; nt < 4; nt++) {
            int col = wn * 32 + nt * 8 + c * 2;
            float b0v = __ldg(cs.bb + col), b1v = __ldg(cs.bb + col + 1);
            acc[mt][nt][0] += b0v; acc[mt][nt][1] += b1v;
            acc[mt][nt][2] += b0v; acc[mt][nt][3] += b1v;
            ss0 += acc[mt][nt][0] * acc[mt][nt][0] + acc[mt][nt][1] * acc[mt][nt][1];
            ss1 += acc[mt][nt][2] * acc[mt][nt][2] + acc[mt][nt][3] * acc[mt][nt][3];
        }
        ss0 += __shfl_xor_sync(0xffffffffu, ss0, 1);
        ss0 += __shfl_xor_sync(0xffffffffu, ss0, 2);
        ss1 += __shfl_xor_sync(0xffffffffu, ss1, 1);
        ss1 += __shfl_xor_sync(0xffffffffu, ss1, 2);
        if (c == 0) {
            atomicAdd(&ssred[wm * 64 + mt * 16 + g],     ss0);
            atomicAdd(&ssred[wm * 64 + mt * 16 + 8 + g], ss1);
        }
    }
    __syncthreads();

#pragma unroll
    for (int mt = 0; mt < 4; mt++) {
        int rl0 = wm * 64 + mt * 16 + g;
        int rl1 = rl0 + 8;
        float inv0 = 1.0f / fmaxf(sqrtf(ssred[rl0]), 1e-12f);
        float inv1 = 1.0f / fmaxf(sqrtf(ssred[rl1]), 1e-12f);
        int gr0 = row0 + rl0;
        int gr1 = row0 + rl1;
#pragma unroll
        for (int nt = 0; nt < 4; nt++) {
            int col = wn * 32 + nt * 8 + c * 2;
            if (gr0 < n) {
                float v0 = acc[mt][nt][0] * inv0;
                float v1 = acc[mt][nt][1] * inv0;
                if (mode == 2) {
                    float2 a2 = *reinterpret_cast<const float2*>(cs.addin + (size_t)gr0 * H + col);
                    v0 += a2.x; v1 += a2.y;
                }
                if (mode >= 1) {
                    v0 = (v0 >= 0.f) ? v0 : 0.01f * v0;
                    v1 = (v1 >= 0.f) ? v1 : 0.01f * v1;
                }
                *reinterpret_cast<float2*>(cs.out + (size_t)gr0 * H + col) = make_float2(v0, v1);
            }
            if (gr1 < n) {
                float v2 = acc[mt][nt][2] * inv1;
                float v3 = acc[mt][nt][3] * inv1;
                if (mode == 2) {
                    float2 a2 = *reinterpret_cast<const float2*>(cs.addin + (size_t)gr1 * H + col);
                    v2 += a2.x; v3 += a2.y;
                }
                if (mode >= 1) {
                    v2 = (v2 >= 0.f) ? v2 : 0.01f * v2;
                    v3 = (v3 >= 0.f) ? v3 : 0.01f * v3;
                }
                *reinterpret_cast<float2*>(cs.out + (size_t)gr1 * H + col) = make_float2(v2, v3);
            }
        }
    }
}

// ---------------- host ----------------
extern "C" void kernel_launch(void* const* d_in, const int* in_sizes, int n_in,
                              void* d_out, int out_size)
{
    const float* x_ip  = (const float*)d_in[0];
    const float* x_con = (const float*)d_in[1];
    const int* src_ipcon = (const int*)d_in[2];
    const int* dst_ipcon = (const int*)d_in[3];
    const int* src_conip = (const int*)d_in[4];
    const int* dst_conip = (const int*)d_in[5];
    const int* src_ipip  = (const int*)d_in[6];
    const int* dst_ipip  = (const int*)d_in[7];
    const int* src_csrc  = (const int*)d_in[8];
    const int* dst_csrc  = (const int*)d_in[9];
    const int* src_cdst  = (const int*)d_in[10];
    const int* dst_cdst  = (const int*)d_in[11];
    const float* Wl_t = (const float*)d_in[12];
    const float* bl_t = (const float*)d_in[13];
    const float* Wr_t = (const float*)d_in[14];
    const float* Wl_s = (const float*)d_in[15];
    const float* bl_s = (const float*)d_in[16];
    const float* Wr_s = (const float*)d_in[17];

    const int n_ip  = in_sizes[0] / H;
    const int n_con = in_sizes[1] / H;
    const int nE_ipcon = in_sizes[2];
    const int nE_conip = in_sizes[4];
    const int nE_ipip  = in_sizes[6];
    const int nE_csrc  = in_sizes[8];
    const int nE_cdst  = in_sizes[10];

    uint32_t *s0, *s1, *s2, *wsp;
    float *tmpC, *ipA, *ipB, *conA, *conB;
    int *cnt, *off, *eidx, *part;
    cudaGetSymbolAddress((void**)&s0,   g_s0);
    cudaGetSymbolAddress((void**)&s1,   g_s1);
    cudaGetSymbolAddress((void**)&s2,   g_s2);
    cudaGetSymbolAddress((void**)&tmpC, g_tmpC);
    cudaGetSymbolAddress((void**)&ipA,  g_ipA);
    cudaGetSymbolAddress((void**)&ipB,  g_ipB);
    cudaGetSymbolAddress((void**)&conA, g_conA);
    cudaGetSymbolAddress((void**)&conB, g_conB);
    cudaGetSymbolAddress((void**)&wsp,  g_wsplit);
    cudaGetSymbolAddress((void**)&cnt,  g_cnt);
    cudaGetSymbolAddress((void**)&off,  g_off);
    cudaGetSymbolAddress((void**)&eidx, g_eidx);
    cudaGetSymbolAddress((void**)&part, g_part);

    cudaFuncSetAttribute(combine_fused_kernel, cudaFuncAttributeMaxDynamicSharedMemorySize, DSMEM_BYTES);

    float* out = (float*)d_out;

    BuildParams bp;
    bp.e[0] = { src_ipip,  dst_ipip,  nE_ipip,  n_ip,  0,                0 };
    bp.e[1] = { src_csrc,  dst_csrc,  nE_csrc,  n_con, n_ip,             nE_ipip };
    bp.e[2] = { src_cdst,  dst_cdst,  nE_cdst,  n_con, n_ip + n_con,     nE_ipip + nE_csrc };
    bp.e[3] = { src_ipcon, dst_ipcon, nE_ipcon, n_con, n_ip + 2 * n_con, nE_ipip + nE_csrc + nE_cdst };
    bp.e[4] = { src_conip, dst_conip, nE_conip, n_ip,  n_ip + 3 * n_con, nE_ipip + nE_csrc + nE_cdst + nE_ipcon };

    int maxE = nE_ipip;
    if (nE_csrc  > maxE) maxE = nE_csrc;
    if (nE_cdst  > maxE) maxE = nE_cdst;
    if (nE_ipcon > maxE) maxE = nE_ipcon;
    if (nE_conip > maxE) maxE = nE_conip;
    const int cntBlocks = (maxE + 255) / 256;

    precount_kernel<<<640 + 5 * cntBlocks, 256>>>(Wl_t, Wr_t, Wl_s, Wr_s, wsp, bp, cnt, cntBlocks);
    scan_phase1<<<dim3(MAXB, 5), 1024>>>(bp, cnt, off, part);
    scan_phase23<<<dim3(MAXB, 5), 1024>>>(bp, off, part);
    fill_kernel<<<dim3(cntBlocks, 5), 256>>>(bp, cnt, off, eidx);

    const int* off0 = off + bp.e[0].dstbase + 0;
    const int* off1 = off + bp.e[1].dstbase + 1;
    const int* off2 = off + bp.e[2].dstbase + 2;
    const int* off3 = off + bp.e[3].dstbase + 3;
    const int* off4 = off + bp.e[4].dstbase + 4;
    const int* ei0 = eidx + bp.e[0].ebase;
    const int* ei1 = eidx + bp.e[1].ebase;
    const int* ei2 = eidx + bp.e[2].ebase;
    const int* ei3 = eidx + bp.e[3].ebase;
    const int* ei4 = eidx + bp.e[4].ebase;

    const int nbIP  = (n_ip  + 255) / 256;
    const int nbCON = (n_con + 255) / 256;
    const int aggBlocksCon = (n_con * 32 + 255) / 256;
    const size_t WSZ = 16384;

    for (int l = 0; l < 2; l++) {
        const float* xi = (l == 0) ? x_ip  : ipB;
        const float* xc = (l == 0) ? x_con : conB;

        const float* b0 = bl_t + (size_t)(l * 3 + 0) * H;
        const float* b1 = bl_t + (size_t)(l * 3 + 1) * H;
        const float* b2 = bl_t + (size_t)(l * 3 + 2) * H;
        const float* bs0 = bl_s + (size_t)(l * 2 + 0) * H;
        const float* bs1 = bl_s + (size_t)(l * 2 + 1) * H;

        // ---------- temporal aggregation (3 segments, fused) ----------
        AggSeg a0 = { xi, off0, ei0, s0, n_ip };
        AggSeg a1 = { xc, off1, ei1, s1, n_con };
        AggSeg a2 = { xc, off2, ei2, s2, n_con };
        agg_fused_kernel<<<dim3(aggBlocksCon, 3), 256>>>(a0, a1, a2);

        // ---------- temporal combines: (con sage1 + ip sage) fused, then con sage2 ----------
        CombSeg cC1 = { s1, xc, wsp + (size_t)(l * 3 + 1) * WSZ, b1, nullptr, tmpC, n_con, nbCON, 0 };
        CombSeg cIP = { s0, xi, wsp + (size_t)(l * 3 + 0) * WSZ, b0, nullptr, ipA,  n_ip,  nbIP,  1 };
        combine_fused_kernel<<<nbCON + nbIP, 512, DSMEM_BYTES>>>(cC1, cIP);

        CombSeg cC2 = { s2, xc, wsp + (size_t)(l * 3 + 2) * WSZ, b2, tmpC, conA, n_con, nbCON, 2 };
        CombSeg cNil = {};
        combine_fused_kernel<<<nbCON, 512, DSMEM_BYTES>>>(cC2, cNil);

        // ---------- spatial aggregation (2 segments, fused) ----------
        AggSeg a3 = { ipA,  off3, ei3, s1, n_con };
        AggSeg a4 = { conA, off4, ei4, s0, n_ip };
        agg_fused_kernel<<<dim3(aggBlocksCon, 2), 256>>>(a3, a4, a4);

        // ---------- spatial combines fused ----------
        float* out_ip  = (l == 1) ? out : ipB;
        float* out_con = (l == 1) ? (out + (size_t)n_ip * H) : conB;

        CombSeg cSC = { s1, conA, wsp + (size_t)(6 + l * 2 + 0) * WSZ, bs0, nullptr, out_con, n_con, nbCON, 1 };
        CombSeg cSI = { s0, ipA,  wsp + (size_t)(6 + l * 2 + 1) * WSZ, bs1, nullptr, out_ip,  n_ip,  nbIP,  1 };
        combine_fused_kernel<<<nbCON + nbIP, 512, DSMEM_BYTES>>>(cSC, cSI);
    }
}

// round 14
// speedup vs baseline: 1.7761x; 1.0319x over previous
#include <cuda_runtime.h>
#include <cuda_fp16.h>
#include <math.h>
#include <stdint.h>

#define H 128
#define N_IP_MAX 50000
#define N_CON_MAX 200000
#define MAXB 256

// ---------------- scratch ----------------
// fp16-permuted feature format: [row][kstep 0..7][slot 0..7] u32 (=256B/row), +256 rows pad
#define IPR (N_IP_MAX + 256)
#define CONR (N_CON_MAX + 256)
__device__ uint32_t g_s0[IPR * 64];
__device__ uint32_t g_s1[CONR * 64];
__device__ uint32_t g_s2[CONR * 64];
__device__ uint32_t g_x16ip[IPR * 64];
__device__ uint32_t g_x16con[CONR * 64];
__device__ uint32_t g_ipA[IPR * 64];
__device__ uint32_t g_ipB[IPR * 64];
__device__ uint32_t g_conA[CONR * 64];
__device__ uint32_t g_conB[CONR * 64];
__device__ float g_tmpC[N_CON_MAX * H];
__device__ uint32_t g_wsplit[10 * 16384];   // per sage: [k-pair][col] fp16x2
__device__ int g_cnt[700032];               // .bss zero; fill counts it back down to zero
__device__ int g_off[700064];
__device__ int g_eidx[1800064];
__device__ int g_part[5 * MAXB];

struct EdgeDesc { const int* src; const int* dst; int nE; int n_dst; int dstbase; int ebase; };
struct BuildParams { EdgeDesc e[5]; };
struct AggSeg { const uint32_t* x; const int* off; const int* eidx; uint32_t* s; int n; };
struct CombSeg {
    const uint32_t* s;     // fp16 permuted agg output
    const uint32_t* xd;    // fp16 permuted dst (root) features
    const uint32_t* w; const float* bb;
    const float* addin;    // fp32 addin (mode 2)
    float* outf; uint32_t* out16;
    int n; int nblk; int mode; int f16out;   // mode: 0 norm, 1 +lrelu, 2 +addin+lrelu
};

// ---------------- helpers ----------------
__device__ __forceinline__ uint32_t packh2(float x0, float x1)
{
    uint32_t r;
    asm("cvt.rn.f16x2.f32 %0, %1, %2;" : "=r"(r) : "f"(x1), "f"(x0));
    return r;
}

__device__ __forceinline__ float2 unpackh2(uint32_t v)
{
    __half2 h = *reinterpret_cast<__half2*>(&v);
    return __half22float2(h);
}

__device__ __forceinline__ void mma16816h(float* d, const uint32_t* a, uint32_t b0, uint32_t b1)
{
    asm volatile(
        "mma.sync.aligned.m16n8k16.row.col.f32.f16.f16.f32 "
        "{%0,%1,%2,%3}, {%4,%5,%6,%7}, {%8,%9}, {%0,%1,%2,%3};"
        : "+f"(d[0]), "+f"(d[1]), "+f"(d[2]), "+f"(d[3])
        : "r"(a[0]), "r"(a[1]), "r"(a[2]), "r"(a[3]), "r"(b0), "r"(b1));
}

__device__ __forceinline__ void cp_async16(uint32_t smem_dst, const void* gsrc)
{
    asm volatile("cp.async.ca.shared.global [%0], [%1], 16;" :: "r"(smem_dst), "l"(gsrc));
}
__device__ __forceinline__ void cp_commit() { asm volatile("cp.async.commit_group;"); }
__device__ __forceinline__ void cp_wait0()  { asm volatile("cp.async.wait_group 0;" ::: "memory"); }

__device__ __forceinline__ int permq(int p) { return (p < 4) ? (2 * p) : (2 * (p - 4) + 1); }

// ---------------- fused presplit + count + input fp16 conversion ----------------
__global__ void precount_kernel(const float* __restrict__ Wl_t, const float* __restrict__ Wr_t,
                                const float* __restrict__ Wl_s, const float* __restrict__ Wr_s,
                                uint32_t* __restrict__ wout, BuildParams bp,
                                int* __restrict__ cnt, int cntBlocks,
                                const float* __restrict__ x_ip, const float* __restrict__ x_con,
                                uint32_t* __restrict__ x16ip, uint32_t* __restrict__ x16con,
                                int n_ip, int n_con, int convIpB, int convConB)
{
    int bx = blockIdx.x;
    if (bx < 640) {
        int sg  = bx >> 6;
        int idx = (bx & 63) * 256 + threadIdx.x;
        int p = idx >> 7;
        int col = idx & 127;
        const float *Wl, *Wr;
        if (sg < 6) { Wl = Wl_t + (size_t)sg * H * H;       Wr = Wr_t + (size_t)sg * H * H; }
        else        { Wl = Wl_s + (size_t)(sg - 6) * H * H; Wr = Wr_s + (size_t)(sg - 6) * H * H; }
        int k0 = 2 * p;
        float x0 = (k0 < H)     ? Wl[k0 * H + col]       : Wr[(k0 - H) * H + col];
        float x1 = (k0 + 1 < H) ? Wl[(k0 + 1) * H + col] : Wr[(k0 + 1 - H) * H + col];
        wout[(size_t)sg * 16384 + idx] = packh2(x0, x1);
        return;
    }
    bx -= 640;
    if (bx < 5 * cntBlocks) {
        int t = bx / cntBlocks;
        int i = (bx % cntBlocks) * 256 + threadIdx.x;
        EdgeDesc d = bp.e[t];
        if (i < d.nE) atomicAdd(&cnt[d.dstbase + d.dst[i]], 1);
        return;
    }
    bx -= 5 * cntBlocks;
    // input conversion: thread = (row, half)
    const float* xsrc;
    uint32_t* xdst;
    int idx, nrows;
    if (bx < convIpB) { xsrc = x_ip;  xdst = x16ip;  idx = bx * 256 + threadIdx.x; nrows = n_ip; }
    else              { xsrc = x_con; xdst = x16con; idx = (bx - convIpB) * 256 + threadIdx.x; nrows = n_con; }
    int row = idx >> 1, hf = idx & 1;
    if (row >= nrows) return;
#pragma unroll
    for (int kt = 0; kt < 8; kt++) {
        const float* ap = xsrc + (size_t)row * H + kt * 16 + hf * 8;
        float4 f0 = *reinterpret_cast<const float4*>(ap);
        float4 f1 = *reinterpret_cast<const float4*>(ap + 4);
        uint32_t* dst = xdst + (size_t)row * 64 + kt * 8;
        dst[permq(hf * 4 + 0)] = packh2(f0.x, f0.y);
        dst[permq(hf * 4 + 1)] = packh2(f0.z, f0.w);
        dst[permq(hf * 4 + 2)] = packh2(f1.x, f1.y);
        dst[permq(hf * 4 + 3)] = packh2(f1.z, f1.w);
    }
}

// ---------------- CSR scans ----------------
__global__ void scan_phase1(BuildParams bp, const int* __restrict__ cnt,
                            int* __restrict__ off, int* __restrict__ part)
{
    int t = blockIdx.y;
    EdgeDesc d = bp.e[t];
    int L = d.n_dst;
    int i = blockIdx.x * 1024 + threadIdx.x;
    __shared__ int sh[1024];
    int v = (i < L) ? cnt[d.dstbase + i] : 0;
    sh[threadIdx.x] = v;
    __syncthreads();
    for (int o = 1; o < 1024; o <<= 1) {
        int x = (threadIdx.x >= o) ? sh[threadIdx.x - o] : 0;
        __syncthreads();
        sh[threadIdx.x] += x;
        __syncthreads();
    }
    if (i < L) off[d.dstbase + t + i] = sh[threadIdx.x] - v;
    if (threadIdx.x == 1023) part[t * MAXB + blockIdx.x] = sh[1023];
}

__global__ void scan_phase23(BuildParams bp, int* __restrict__ off, const int* __restrict__ part)
{
    int t = blockIdx.y;
    EdgeDesc d = bp.e[t];
    int L = d.n_dst;
    __shared__ int pref[MAXB];
    if (threadIdx.x < MAXB) pref[threadIdx.x] = part[t * MAXB + threadIdx.x];
    __syncthreads();
    for (int o = 1; o < MAXB; o <<= 1) {
        int x = 0;
        if (threadIdx.x < MAXB && threadIdx.x >= o) x = pref[threadIdx.x - o];
        __syncthreads();
        if (threadIdx.x < MAXB) pref[threadIdx.x] += x;
        __syncthreads();
    }
    int add = (blockIdx.x == 0) ? 0 : pref[blockIdx.x - 1];
    int i = blockIdx.x * 1024 + threadIdx.x;
    if (i < L) off[d.dstbase + t + i] += add;
    if (blockIdx.x == 0 && threadIdx.x == 0) off[d.dstbase + t + L] = d.nE;
}

__global__ void fill_kernel(BuildParams bp, int* __restrict__ cnt,
                            const int* __restrict__ off, int* __restrict__ eidx)
{
    int t = blockIdx.y;
    EdgeDesc d = bp.e[t];
    int i = blockIdx.x * blockDim.x + threadIdx.x;
    if (i >= d.nE) return;
    int dd = d.dst[i];
    int pos = off[d.dstbase + t + dd] + atomicAdd(&cnt[d.dstbase + dd], -1) - 1;
    eidx[d.ebase + pos] = d.src[i];
}

// ---------------- fused CSR mean-aggregation, fp16 in / fp16 out ----------------
// warp per dst row; lane covers u32 slots 2*lane, 2*lane+1 (elementwise, layout-agnostic)
__global__ void agg_fused_kernel(AggSeg a0, AggSeg a1, AggSeg a2)
{
    AggSeg sg;
    if (blockIdx.y == 0) sg = a0;
    else if (blockIdx.y == 1) sg = a1;
    else sg = a2;
    int w = (blockIdx.x * blockDim.x + threadIdx.x) >> 5;
    int lane = threadIdx.x & 31;
    if (w >= sg.n) return;
    int start = sg.off[w], end = sg.off[w + 1];
    float4 acc = make_float4(0.f, 0.f, 0.f, 0.f);
    for (int e = start; e < end; e++) {
        int si = __ldg(sg.eidx + e);
        uint2 v = reinterpret_cast<const uint2*>(sg.x)[(size_t)si * 32 + lane];
        float2 f0 = unpackh2(v.x), f1 = unpackh2(v.y);
        acc.x += f0.x; acc.y += f0.y; acc.z += f1.x; acc.w += f1.y;
    }
    float inv = 1.0f / (float)max(end - start, 1);
    uint2 o;
    o.x = packh2(acc.x * inv, acc.y * inv);
    o.y = packh2(acc.z * inv, acc.w * inv);
    reinterpret_cast<uint2*>(sg.s)[(size_t)w * 32 + lane] = o;
}

// ---------------- fused SAGE combine: fully-resident A, all-cp.async staging ------
#define WSTRIDE 132
#define DSMEM_BYTES ((16 * 2048 + 128 * WSTRIDE) * 4)

__global__ void __launch_bounds__(512) combine_fused_kernel(CombSeg A, CombSeg B)
{
    extern __shared__ uint32_t dyn[];
    uint32_t* Asm = dyn;                 // [kt][row*8+slot]
    uint32_t* Wsm = dyn + 16 * 2048;
    __shared__ float ssred[256];

    CombSeg cs;
    int blk = blockIdx.x;
    if (blk < A.nblk) cs = A;
    else { blk -= A.nblk; cs = B; }

    const int tid  = threadIdx.x;
    const int row0 = blk * 256;
    const int n    = cs.n;
    const int mode = cs.mode;

    const uint32_t ab = (uint32_t)__cvta_generic_to_shared(Asm);
    const uint32_t wb = (uint32_t)__cvta_generic_to_shared(Wsm);

    // ---- stage W (66KB) ----
#pragma unroll
    for (int it = 0; it < 8; it++) {
        int ch = tid + it * 512;
        int p = ch >> 5, o = ch & 31;
        cp_async16(wb + (uint32_t)(p * WSTRIDE + o * 4) * 4, cs.w + p * 128 + o * 4);
    }
    // ---- stage s-half (ksteps 0..7) and xdst-half (ksteps 8..15), both fp16 ----
    {
        int row = tid >> 1, hf = tid & 1;
        const uint32_t* srow = cs.s  + (size_t)(row0 + row) * 64 + hf * 4;
        const uint32_t* xrow = cs.xd + (size_t)(row0 + row) * 64 + hf * 4;
#pragma unroll
        for (int kt = 0; kt < 8; kt++) {
            cp_async16(ab + (uint32_t)(kt * 2048 + row * 8 + hf * 4) * 4, srow + kt * 8);
            cp_async16(ab + (uint32_t)((8 + kt) * 2048 + row * 8 + hf * 4) * 4, xrow + kt * 8);
        }
    }
    cp_commit();

    if (tid < 256) ssred[tid] = 0.0f;

    cp_wait0();
    __syncthreads();

    // ---- mma mapping ----
    const int lane = tid & 31;
    const int wid  = tid >> 5;
    const int wm   = wid >> 2;
    const int wn   = wid & 3;
    const int g    = lane >> 2;
    const int c    = lane & 3;

    float acc[4][4][4];
#pragma unroll
    for (int mt = 0; mt < 4; mt++)
#pragma unroll
        for (int nt = 0; nt < 4; nt++)
#pragma unroll
            for (int j = 0; j < 4; j++) acc[mt][nt][j] = 0.0f;

    // ---- barrier-free MMA loop over 16 resident k-steps ----
#pragma unroll 4
    for (int kt = 0; kt < 16; kt++) {
        const uint32_t* cur = Asm + kt * 2048;
        uint32_t ahf[4][4];
#pragma unroll
        for (int mt = 0; mt < 4; mt++) {
            int R = wm * 64 + mt * 16;
            uint2 v0 = *reinterpret_cast<const uint2*>(&cur[(R + g) * 8 + c * 2]);
            uint2 v1 = *reinterpret_cast<const uint2*>(&cur[(R + g + 8) * 8 + c * 2]);
            ahf[mt][0] = v0.x; ahf[mt][1] = v1.x; ahf[mt][2] = v0.y; ahf[mt][3] = v1.y;
        }
#pragma unroll
        for (int nt = 0; nt < 4; nt++) {
            int col = wn * 32 + nt * 8 + g;
            uint32_t w0 = Wsm[(kt * 8 + c) * WSTRIDE + col];
            uint32_t w1 = Wsm[(kt * 8 + c + 4) * WSTRIDE + col];
#pragma unroll
            for (int mt = 0; mt < 4; mt++)
                mma16816h(acc[mt][nt], ahf[mt], w0, w1);
        }
    }

    // ---- epilogue ----
#pragma unroll
    for (int mt = 0; mt < 4; mt++) {
        float ss0 = 0.0f, ss1 = 0.0f;
#pragma unroll
        for (int nt = 0; nt < 4; nt++) {
            int col = wn * 32 + nt * 8 + c * 2;
            float b0v = __ldg(cs.bb + col), b1v = __ldg(cs.bb + col + 1);
            acc[mt][nt][0] += b0v; acc[mt][nt][1] += b1v;
            acc[mt][nt][2] += b0v; acc[mt][nt][3] += b1v;
            ss0 += acc[mt][nt][0] * acc[mt][nt][0] + acc[mt][nt][1] * acc[mt][nt][1];
            ss1 += acc[mt][nt][2] * acc[mt][nt][2] + acc[mt][nt][3] * acc[mt][nt][3];
        }
        ss0 += __shfl_xor_sync(0xffffffffu, ss0, 1);
        ss0 += __shfl_xor_sync(0xffffffffu, ss0, 2);
        ss1 += __shfl_xor_sync(0xffffffffu, ss1, 1);
        ss1 += __shfl_xor_sync(0xffffffffu, ss1, 2);
        if (c == 0) {
            atomicAdd(&ssred[wm * 64 + mt * 16 + g],     ss0);
            atomicAdd(&ssred[wm * 64 + mt * 16 + 8 + g], ss1);
        }
    }
    __syncthreads();

#pragma unroll
    for (int mt = 0; mt < 4; mt++) {
        int rl0 = wm * 64 + mt * 16 + g;
        int rl1 = rl0 + 8;
        float inv0 = 1.0f / fmaxf(sqrtf(ssred[rl0]), 1e-12f);
        float inv1 = 1.0f / fmaxf(sqrtf(ssred[rl1]), 1e-12f);
        int gr0 = row0 + rl0;
        int gr1 = row0 + rl1;
#pragma unroll
        for (int nt = 0; nt < 4; nt++) {
            int col = wn * 32 + nt * 8 + c * 2;
            int kstep = wn * 2 + (nt >> 1);
            int slot  = permq((nt & 1) * 4 + c);
            if (gr0 < n) {
                float v0 = acc[mt][nt][0] * inv0;
                float v1 = acc[mt][nt][1] * inv0;
                if (mode == 2) {
                    float2 a2 = *reinterpret_cast<const float2*>(cs.addin + (size_t)gr0 * H + col);
                    v0 += a2.x; v1 += a2.y;
                }
                if (mode >= 1) {
                    v0 = (v0 >= 0.f) ? v0 : 0.01f * v0;
                    v1 = (v1 >= 0.f) ? v1 : 0.01f * v1;
                }
                if (cs.f16out)
                    cs.out16[(size_t)gr0 * 64 + kstep * 8 + slot] = packh2(v0, v1);
                else
                    *reinterpret_cast<float2*>(cs.outf + (size_t)gr0 * H + col) = make_float2(v0, v1);
            }
            if (gr1 < n) {
                float v2 = acc[mt][nt][2] * inv1;
                float v3 = acc[mt][nt][3] * inv1;
                if (mode == 2) {
                    float2 a2 = *reinterpret_cast<const float2*>(cs.addin + (size_t)gr1 * H + col);
                    v2 += a2.x; v3 += a2.y;
                }
                if (mode >= 1) {
                    v2 = (v2 >= 0.f) ? v2 : 0.01f * v2;
                    v3 = (v3 >= 0.f) ? v3 : 0.01f * v3;
                }
                if (cs.f16out)
                    cs.out16[(size_t)gr1 * 64 + kstep * 8 + slot] = packh2(v2, v3);
                else
                    *reinterpret_cast<float2*>(cs.outf + (size_t)gr1 * H + col) = make_float2(v2, v3);
            }
        }
    }
}

// ---------------- host ----------------
extern "C" void kernel_launch(void* const* d_in, const int* in_sizes, int n_in,
                              void* d_out, int out_size)
{
    const float* x_ip  = (const float*)d_in[0];
    const float* x_con = (const float*)d_in[1];
    const int* src_ipcon = (const int*)d_in[2];
    const int* dst_ipcon = (const int*)d_in[3];
    const int* src_conip = (const int*)d_in[4];
    const int* dst_conip = (const int*)d_in[5];
    const int* src_ipip  = (const int*)d_in[6];
    const int* dst_ipip  = (const int*)d_in[7];
    const int* src_csrc  = (const int*)d_in[8];
    const int* dst_csrc  = (const int*)d_in[9];
    const int* src_cdst  = (const int*)d_in[10];
    const int* dst_cdst  = (const int*)d_in[11];
    const float* Wl_t = (const float*)d_in[12];
    const float* bl_t = (const float*)d_in[13];
    const float* Wr_t = (const float*)d_in[14];
    const float* Wl_s = (const float*)d_in[15];
    const float* bl_s = (const float*)d_in[16];
    const float* Wr_s = (const float*)d_in[17];

    const int n_ip  = in_sizes[0] / H;
    const int n_con = in_sizes[1] / H;
    const int nE_ipcon = in_sizes[2];
    const int nE_conip = in_sizes[4];
    const int nE_ipip  = in_sizes[6];
    const int nE_csrc  = in_sizes[8];
    const int nE_cdst  = in_sizes[10];

    uint32_t *s0, *s1, *s2, *wsp, *x16ip, *x16con, *ipA, *ipB, *conA, *conB;
    float *tmpC;
    int *cnt, *off, *eidx, *part;
    cudaGetSymbolAddress((void**)&s0,     g_s0);
    cudaGetSymbolAddress((void**)&s1,     g_s1);
    cudaGetSymbolAddress((void**)&s2,     g_s2);
    cudaGetSymbolAddress((void**)&x16ip,  g_x16ip);
    cudaGetSymbolAddress((void**)&x16con, g_x16con);
    cudaGetSymbolAddress((void**)&ipA,    g_ipA);
    cudaGetSymbolAddress((void**)&ipB,    g_ipB);
    cudaGetSymbolAddress((void**)&conA,   g_conA);
    cudaGetSymbolAddress((void**)&conB,   g_conB);
    cudaGetSymbolAddress((void**)&tmpC,   g_tmpC);
    cudaGetSymbolAddress((void**)&wsp,    g_wsplit);
    cudaGetSymbolAddress((void**)&cnt,    g_cnt);
    cudaGetSymbolAddress((void**)&off,    g_off);
    cudaGetSymbolAddress((void**)&eidx,   g_eidx);
    cudaGetSymbolAddress((void**)&part,   g_part);

    cudaFuncSetAttribute(combine_fused_kernel, cudaFuncAttributeMaxDynamicSharedMemorySize, DSMEM_BYTES);

    float* out = (float*)d_out;

    BuildParams bp;
    bp.e[0] = { src_ipip,  dst_ipip,  nE_ipip,  n_ip,  0,                0 };
    bp.e[1] = { src_csrc,  dst_csrc,  nE_csrc,  n_con, n_ip,             nE_ipip };
    bp.e[2] = { src_cdst,  dst_cdst,  nE_cdst,  n_con, n_ip + n_con,     nE_ipip + nE_csrc };
    bp.e[3] = { src_ipcon, dst_ipcon, nE_ipcon, n_con, n_ip + 2 * n_con, nE_ipip + nE_csrc + nE_cdst };
    bp.e[4] = { src_conip, dst_conip, nE_conip, n_ip,  n_ip + 3 * n_con, nE_ipip + nE_csrc + nE_cdst + nE_ipcon };

    int maxE = nE_ipip;
    if (nE_csrc  > maxE) maxE = nE_csrc;
    if (nE_cdst  > maxE) maxE = nE_cdst;
    if (nE_ipcon > maxE) maxE = nE_ipcon;
    if (nE_conip > maxE) maxE = nE_conip;
    const int cntBlocks  = (maxE + 255) / 256;
    const int convIpB  = (n_ip * 2 + 255) / 256;
    const int convConB = (n_con * 2 + 255) / 256;

    precount_kernel<<<640 + 5 * cntBlocks + convIpB + convConB, 256>>>(
        Wl_t, Wr_t, Wl_s, Wr_s, wsp, bp, cnt, cntBlocks,
        x_ip, x_con, x16ip, x16con, n_ip, n_con, convIpB, convConB);
    scan_phase1<<<dim3(MAXB, 5), 1024>>>(bp, cnt, off, part);
    scan_phase23<<<dim3(MAXB, 5), 1024>>>(bp, off, part);
    fill_kernel<<<dim3(cntBlocks, 5), 256>>>(bp, cnt, off, eidx);

    const int* off0 = off + bp.e[0].dstbase + 0;
    const int* off1 = off + bp.e[1].dstbase + 1;
    const int* off2 = off + bp.e[2].dstbase + 2;
    const int* off3 = off + bp.e[3].dstbase + 3;
    const int* off4 = off + bp.e[4].dstbase + 4;
    const int* ei0 = eidx + bp.e[0].ebase;
    const int* ei1 = eidx + bp.e[1].ebase;
    const int* ei2 = eidx + bp.e[2].ebase;
    const int* ei3 = eidx + bp.e[3].ebase;
    const int* ei4 = eidx + bp.e[4].ebase;

    const int nbIP  = (n_ip  + 255) / 256;
    const int nbCON = (n_con + 255) / 256;
    const int aggBlocksCon = (n_con * 32 + 255) / 256;
    const size_t WSZ = 16384;

    for (int l = 0; l < 2; l++) {
        const uint32_t* xi = (l == 0) ? x16ip  : ipB;
        const uint32_t* xc = (l == 0) ? x16con : conB;

        const float* b0 = bl_t + (size_t)(l * 3 + 0) * H;
        const float* b1 = bl_t + (size_t)(l * 3 + 1) * H;
        const float* b2 = bl_t + (size_t)(l * 3 + 2) * H;
        const float* bs0 = bl_s + (size_t)(l * 2 + 0) * H;
        const float* bs1 = bl_s + (size_t)(l * 2 + 1) * H;

        // ---------- temporal aggregation (3 segments, fused) ----------
        AggSeg a0 = { xi, off0, ei0, s0, n_ip };
        AggSeg a1 = { xc, off1, ei1, s1, n_con };
        AggSeg a2 = { xc, off2, ei2, s2, n_con };
        agg_fused_kernel<<<dim3(aggBlocksCon, 3), 256>>>(a0, a1, a2);

        // ---------- temporal combines ----------
        CombSeg cC1 = { s1, xc, wsp + (size_t)(l * 3 + 1) * WSZ, b1, nullptr, tmpC, nullptr, n_con, nbCON, 0, 0 };
        CombSeg cIP = { s0, xi, wsp + (size_t)(l * 3 + 0) * WSZ, b0, nullptr, nullptr, ipA,  n_ip,  nbIP,  1, 1 };
        combine_fused_kernel<<<nbCON + nbIP, 512, DSMEM_BYTES>>>(cC1, cIP);

        CombSeg cC2 = { s2, xc, wsp + (size_t)(l * 3 + 2) * WSZ, b2, tmpC, nullptr, conA, n_con, nbCON, 2, 1 };
        CombSeg cNil = {};
        combine_fused_kernel<<<nbCON, 512, DSMEM_BYTES>>>(cC2, cNil);

        // ---------- spatial aggregation (2 segments, fused) ----------
        AggSeg a3 = { ipA,  off3, ei3, s1, n_con };
        AggSeg a4 = { conA, off4, ei4, s0, n_ip };
        agg_fused_kernel<<<dim3(aggBlocksCon, 2), 256>>>(a3, a4, a4);

        // ---------- spatial combines fused ----------
        if (l == 0) {
            CombSeg cSC = { s1, conA, wsp + (size_t)(6 + 0) * WSZ, bs0, nullptr, nullptr, conB, n_con, nbCON, 1, 1 };
            CombSeg cSI = { s0, ipA,  wsp + (size_t)(6 + 1) * WSZ, bs1, nullptr, nullptr, ipB,  n_ip,  nbIP,  1, 1 };
            combine_fused_kernel<<<nbCON + nbIP, 512, DSMEM_BYTES>>>(cSC, cSI);
        } else {
            CombSeg cSC = { s1, conA, wsp + (size_t)(6 + 2) * WSZ, bs0, nullptr, out + (size_t)n_ip * H, nullptr, n_con, nbCON, 1, 0 };
            CombSeg cSI = { s0, ipA,  wsp + (size_t)(6 + 3) * WSZ, bs1, nullptr, out, nullptr, n_ip,  nbIP,  1, 0 };
            combine_fused_kernel<<<nbCON + nbIP, 512, DSMEM_BYTES>>>(cSC, cSI);
        }
    }
}

// round 15
// speedup vs baseline: 1.9946x; 1.1230x over previous
#include <cuda_runtime.h>
#include <cuda_fp16.h>
#include <math.h>
#include <stdint.h>

#define H 128
#define N_IP_MAX 50000
#define N_CON_MAX 200000
#define MAXB 256

// ---------------- scratch ----------------
// fp16-permuted feature format: [row][kstep 0..7][slot 0..7] u32 (=256B/row), +256 rows pad
#define IPR (N_IP_MAX + 256)
#define CONR (N_CON_MAX + 256)
__device__ uint32_t g_s0[IPR * 64];
__device__ uint32_t g_s1[CONR * 64];
__device__ uint32_t g_s2[CONR * 64];
__device__ uint32_t g_x16ip[IPR * 64];
__device__ uint32_t g_x16con[CONR * 64];
__device__ uint32_t g_ipA[IPR * 64];
__device__ uint32_t g_ipB[IPR * 64];
__device__ uint32_t g_conA[CONR * 64];
__device__ uint32_t g_conB[CONR * 64];
__device__ uint32_t g_tmpC[CONR * 64];      // fp16 permuted intermediate
__device__ uint32_t g_wsplit[10 * 16384];   // per sage: [k-pair][col] fp16x2
__device__ int g_cnt[700032];               // .bss zero; fill counts it back down to zero
__device__ int g_off[700064];
__device__ int g_eidx[1800064];
__device__ int g_part[5 * MAXB];

struct EdgeDesc { const int* src; const int* dst; int nE; int n_dst; int dstbase; int ebase; };
struct BuildParams { EdgeDesc e[5]; };
struct AggSeg { const uint32_t* x; const int* off; const int* eidx; uint32_t* s; int n; };
struct CombSeg {
    const uint32_t* s;     // fp16 permuted agg output
    const uint32_t* xd;    // fp16 permuted dst (root) features
    const uint32_t* w; const float* bb;
    const uint32_t* addin16;  // fp16 permuted addin (mode 2)
    float* outf; uint32_t* out16;
    int n; int nblk; int mode; int f16out;   // mode: 0 norm, 1 +lrelu, 2 +addin+lrelu
};

// ---------------- helpers ----------------
__device__ __forceinline__ uint32_t packh2(float x0, float x1)
{
    uint32_t r;
    asm("cvt.rn.f16x2.f32 %0, %1, %2;" : "=r"(r) : "f"(x1), "f"(x0));
    return r;
}

__device__ __forceinline__ float2 unpackh2(uint32_t v)
{
    __half2 h = *reinterpret_cast<__half2*>(&v);
    return __half22float2(h);
}

__device__ __forceinline__ void mma16816h(float* d, const uint32_t* a, uint32_t b0, uint32_t b1)
{
    asm volatile(
        "mma.sync.aligned.m16n8k16.row.col.f32.f16.f16.f32 "
        "{%0,%1,%2,%3}, {%4,%5,%6,%7}, {%8,%9}, {%0,%1,%2,%3};"
        : "+f"(d[0]), "+f"(d[1]), "+f"(d[2]), "+f"(d[3])
        : "r"(a[0]), "r"(a[1]), "r"(a[2]), "r"(a[3]), "r"(b0), "r"(b1));
}

__device__ __forceinline__ void cp_async16(uint32_t smem_dst, const void* gsrc)
{
    asm volatile("cp.async.ca.shared.global [%0], [%1], 16;" :: "r"(smem_dst), "l"(gsrc));
}
__device__ __forceinline__ void cp_commit() { asm volatile("cp.async.commit_group;"); }
__device__ __forceinline__ void cp_wait0()  { asm volatile("cp.async.wait_group 0;" ::: "memory"); }

__device__ __forceinline__ int permq(int p) { return (p < 4) ? (2 * p) : (2 * (p - 4) + 1); }

// ---------------- fused presplit + count + input fp16 conversion ----------------
__global__ void precount_kernel(const float* __restrict__ Wl_t, const float* __restrict__ Wr_t,
                                const float* __restrict__ Wl_s, const float* __restrict__ Wr_s,
                                uint32_t* __restrict__ wout, BuildParams bp,
                                int* __restrict__ cnt, int cntBlocks,
                                const float* __restrict__ x_ip, const float* __restrict__ x_con,
                                uint32_t* __restrict__ x16ip, uint32_t* __restrict__ x16con,
                                int n_ip, int n_con, int convIpB, int convConB)
{
    int bx = blockIdx.x;
    if (bx < 640) {
        int sg  = bx >> 6;
        int idx = (bx & 63) * 256 + threadIdx.x;
        int p = idx >> 7;
        int col = idx & 127;
        const float *Wl, *Wr;
        if (sg < 6) { Wl = Wl_t + (size_t)sg * H * H;       Wr = Wr_t + (size_t)sg * H * H; }
        else        { Wl = Wl_s + (size_t)(sg - 6) * H * H; Wr = Wr_s + (size_t)(sg - 6) * H * H; }
        int k0 = 2 * p;
        float x0 = (k0 < H)     ? Wl[k0 * H + col]       : Wr[(k0 - H) * H + col];
        float x1 = (k0 + 1 < H) ? Wl[(k0 + 1) * H + col] : Wr[(k0 + 1 - H) * H + col];
        wout[(size_t)sg * 16384 + idx] = packh2(x0, x1);
        return;
    }
    bx -= 640;
    if (bx < 5 * cntBlocks) {
        int t = bx / cntBlocks;
        int i = (bx % cntBlocks) * 256 + threadIdx.x;
        EdgeDesc d = bp.e[t];
        if (i < d.nE) atomicAdd(&cnt[d.dstbase + d.dst[i]], 1);
        return;
    }
    bx -= 5 * cntBlocks;
    const float* xsrc;
    uint32_t* xdst;
    int idx, nrows;
    if (bx < convIpB) { xsrc = x_ip;  xdst = x16ip;  idx = bx * 256 + threadIdx.x; nrows = n_ip; }
    else              { xsrc = x_con; xdst = x16con; idx = (bx - convIpB) * 256 + threadIdx.x; nrows = n_con; }
    int row = idx >> 1, hf = idx & 1;
    if (row >= nrows) return;
#pragma unroll
    for (int kt = 0; kt < 8; kt++) {
        const float* ap = xsrc + (size_t)row * H + kt * 16 + hf * 8;
        float4 f0 = *reinterpret_cast<const float4*>(ap);
        float4 f1 = *reinterpret_cast<const float4*>(ap + 4);
        uint32_t* dst = xdst + (size_t)row * 64 + kt * 8;
        dst[permq(hf * 4 + 0)] = packh2(f0.x, f0.y);
        dst[permq(hf * 4 + 1)] = packh2(f0.z, f0.w);
        dst[permq(hf * 4 + 2)] = packh2(f1.x, f1.y);
        dst[permq(hf * 4 + 3)] = packh2(f1.z, f1.w);
    }
}

// ---------------- CSR scans ----------------
__global__ void scan_phase1(BuildParams bp, const int* __restrict__ cnt,
                            int* __restrict__ off, int* __restrict__ part)
{
    int t = blockIdx.y;
    EdgeDesc d = bp.e[t];
    int L = d.n_dst;
    int i = blockIdx.x * 1024 + threadIdx.x;
    __shared__ int sh[1024];
    int v = (i < L) ? cnt[d.dstbase + i] : 0;
    sh[threadIdx.x] = v;
    __syncthreads();
    for (int o = 1; o < 1024; o <<= 1) {
        int x = (threadIdx.x >= o) ? sh[threadIdx.x - o] : 0;
        __syncthreads();
        sh[threadIdx.x] += x;
        __syncthreads();
    }
    if (i < L) off[d.dstbase + t + i] = sh[threadIdx.x] - v;
    if (threadIdx.x == 1023) part[t * MAXB + blockIdx.x] = sh[1023];
}

__global__ void scan_phase23(BuildParams bp, int* __restrict__ off, const int* __restrict__ part)
{
    int t = blockIdx.y;
    EdgeDesc d = bp.e[t];
    int L = d.n_dst;
    __shared__ int pref[MAXB];
    if (threadIdx.x < MAXB) pref[threadIdx.x] = part[t * MAXB + threadIdx.x];
    __syncthreads();
    for (int o = 1; o < MAXB; o <<= 1) {
        int x = 0;
        if (threadIdx.x < MAXB && threadIdx.x >= o) x = pref[threadIdx.x - o];
        __syncthreads();
        if (threadIdx.x < MAXB) pref[threadIdx.x] += x;
        __syncthreads();
    }
    int add = (blockIdx.x == 0) ? 0 : pref[blockIdx.x - 1];
    int i = blockIdx.x * 1024 + threadIdx.x;
    if (i < L) off[d.dstbase + t + i] += add;
    if (blockIdx.x == 0 && threadIdx.x == 0) off[d.dstbase + t + L] = d.nE;
}

__global__ void fill_kernel(BuildParams bp, int* __restrict__ cnt,
                            const int* __restrict__ off, int* __restrict__ eidx)
{
    int t = blockIdx.y;
    EdgeDesc d = bp.e[t];
    int i = blockIdx.x * blockDim.x + threadIdx.x;
    if (i >= d.nE) return;
    int dd = d.dst[i];
    int pos = off[d.dstbase + t + dd] + atomicAdd(&cnt[d.dstbase + dd], -1) - 1;
    eidx[d.ebase + pos] = d.src[i];
}

// ---------------- fused CSR mean-aggregation: 2 rows/warp, uint4 lanes ----------------
__global__ void agg_fused_kernel(AggSeg a0, AggSeg a1, AggSeg a2)
{
    AggSeg sg;
    if (blockIdx.y == 0) sg = a0;
    else if (blockIdx.y == 1) sg = a1;
    else sg = a2;
    int gw = (blockIdx.x * blockDim.x + threadIdx.x) >> 5;
    int lane = threadIdx.x & 31;
    int row = gw * 2 + (lane >> 4);
    int sub = lane & 15;
    if (row >= sg.n) return;
    int start = __ldg(sg.off + row), end = __ldg(sg.off + row + 1);
    float acc[8];
#pragma unroll
    for (int j = 0; j < 8; j++) acc[j] = 0.0f;
    for (int e = start; e < end; e++) {
        int si = __ldg(sg.eidx + e);
        uint4 v = reinterpret_cast<const uint4*>(sg.x)[(size_t)si * 16 + sub];
        float2 f0 = unpackh2(v.x), f1 = unpackh2(v.y);
        float2 f2 = unpackh2(v.z), f3 = unpackh2(v.w);
        acc[0] += f0.x; acc[1] += f0.y; acc[2] += f1.x; acc[3] += f1.y;
        acc[4] += f2.x; acc[5] += f2.y; acc[6] += f3.x; acc[7] += f3.y;
    }
    float inv = 1.0f / (float)max(end - start, 1);
    uint4 o;
    o.x = packh2(acc[0] * inv, acc[1] * inv);
    o.y = packh2(acc[2] * inv, acc[3] * inv);
    o.z = packh2(acc[4] * inv, acc[5] * inv);
    o.w = packh2(acc[6] * inv, acc[7] * inv);
    reinterpret_cast<uint4*>(sg.s)[(size_t)row * 16 + sub] = o;
}

// ---------------- fused SAGE combine: fully-resident A, all-cp.async staging ------
#define WSTRIDE 132
#define DSMEM_BYTES ((16 * 2048 + 128 * WSTRIDE) * 4)

__global__ void __launch_bounds__(512) combine_fused_kernel(CombSeg A, CombSeg B)
{
    extern __shared__ uint32_t dyn[];
    uint32_t* Asm = dyn;                 // [kt][row*8+slot]
    uint32_t* Wsm = dyn + 16 * 2048;
    __shared__ float ssred[256];

    CombSeg cs;
    int blk = blockIdx.x;
    if (blk < A.nblk) cs = A;
    else { blk -= A.nblk; cs = B; }

    const int tid  = threadIdx.x;
    const int row0 = blk * 256;
    const int n    = cs.n;
    const int mode = cs.mode;

    const uint32_t ab = (uint32_t)__cvta_generic_to_shared(Asm);
    const uint32_t wb = (uint32_t)__cvta_generic_to_shared(Wsm);

    // ---- stage W (66KB) ----
#pragma unroll
    for (int it = 0; it < 8; it++) {
        int ch = tid + it * 512;
        int p = ch >> 5, o = ch & 31;
        cp_async16(wb + (uint32_t)(p * WSTRIDE + o * 4) * 4, cs.w + p * 128 + o * 4);
    }
    // ---- stage s-half (ksteps 0..7) and xdst-half (ksteps 8..15), both fp16 ----
    {
        int row = tid >> 1, hf = tid & 1;
        const uint32_t* srow = cs.s  + (size_t)(row0 + row) * 64 + hf * 4;
        const uint32_t* xrow = cs.xd + (size_t)(row0 + row) * 64 + hf * 4;
#pragma unroll
        for (int kt = 0; kt < 8; kt++) {
            cp_async16(ab + (uint32_t)(kt * 2048 + row * 8 + hf * 4) * 4, srow + kt * 8);
            cp_async16(ab + (uint32_t)((8 + kt) * 2048 + row * 8 + hf * 4) * 4, xrow + kt * 8);
        }
    }
    cp_commit();

    if (tid < 256) ssred[tid] = 0.0f;

    cp_wait0();
    __syncthreads();

    // ---- mma mapping ----
    const int lane = tid & 31;
    const int wid  = tid >> 5;
    const int wm   = wid >> 2;
    const int wn   = wid & 3;
    const int g    = lane >> 2;
    const int c    = lane & 3;

    float acc[4][4][4];
#pragma unroll
    for (int mt = 0; mt < 4; mt++)
#pragma unroll
        for (int nt = 0; nt < 4; nt++)
#pragma unroll
            for (int j = 0; j < 4; j++) acc[mt][nt][j] = 0.0f;

    // ---- barrier-free MMA loop over 16 resident k-steps ----
#pragma unroll 4
    for (int kt = 0; kt < 16; kt++) {
        const uint32_t* cur = Asm + kt * 2048;
        uint32_t ahf[4][4];
#pragma unroll
        for (int mt = 0; mt < 4; mt++) {
            int R = wm * 64 + mt * 16;
            uint2 v0 = *reinterpret_cast<const uint2*>(&cur[(R + g) * 8 + c * 2]);
            uint2 v1 = *reinterpret_cast<const uint2*>(&cur[(R + g + 8) * 8 + c * 2]);
            ahf[mt][0] = v0.x; ahf[mt][1] = v1.x; ahf[mt][2] = v0.y; ahf[mt][3] = v1.y;
        }
#pragma unroll
        for (int nt = 0; nt < 4; nt++) {
            int col = wn * 32 + nt * 8 + g;
            uint32_t w0 = Wsm[(kt * 8 + c) * WSTRIDE + col];
            uint32_t w1 = Wsm[(kt * 8 + c + 4) * WSTRIDE + col];
#pragma unroll
            for (int mt = 0; mt < 4; mt++)
                mma16816h(acc[mt][nt], ahf[mt], w0, w1);
        }
    }

    // ---- epilogue ----
#pragma unroll
    for (int mt = 0; mt < 4; mt++) {
        float ss0 = 0.0f, ss1 = 0.0f;
#pragma unroll
        for (int nt = 0; nt < 4; nt++) {
            int col = wn * 32 + nt * 8 + c * 2;
            float b0v = __ldg(cs.bb + col), b1v = __ldg(cs.bb + col + 1);
            acc[mt][nt][0] += b0v; acc[mt][nt][1] += b1v;
            acc[mt][nt][2] += b0v; acc[mt][nt][3] += b1v;
            ss0 += acc[mt][nt][0] * acc[mt][nt][0] + acc[mt][nt][1] * acc[mt][nt][1];
            ss1 += acc[mt][nt][2] * acc[mt][nt][2] + acc[mt][nt][3] * acc[mt][nt][3];
        }
        ss0 += __shfl_xor_sync(0xffffffffu, ss0, 1);
        ss0 += __shfl_xor_sync(0xffffffffu, ss0, 2);
        ss1 += __shfl_xor_sync(0xffffffffu, ss1, 1);
        ss1 += __shfl_xor_sync(0xffffffffu, ss1, 2);
        if (c == 0) {
            atomicAdd(&ssred[wm * 64 + mt * 16 + g],     ss0);
            atomicAdd(&ssred[wm * 64 + mt * 16 + 8 + g], ss1);
        }
    }
    __syncthreads();

#pragma unroll
    for (int mt = 0; mt < 4; mt++) {
        int rl0 = wm * 64 + mt * 16 + g;
        int rl1 = rl0 + 8;
        float inv0 = 1.0f / fmaxf(sqrtf(ssred[rl0]), 1e-12f);
        float inv1 = 1.0f / fmaxf(sqrtf(ssred[rl1]), 1e-12f);
        int gr0 = row0 + rl0;
        int gr1 = row0 + rl1;
#pragma unroll
        for (int nt = 0; nt < 4; nt++) {
            int col = wn * 32 + nt * 8 + c * 2;
            int kstep = wn * 2 + (nt >> 1);
            int slot  = permq((nt & 1) * 4 + c);
            if (gr0 < n) {
                float v0 = acc[mt][nt][0] * inv0;
                float v1 = acc[mt][nt][1] * inv0;
                if (mode == 2) {
                    float2 a2 = unpackh2(cs.addin16[(size_t)gr0 * 64 + kstep * 8 + slot]);
                    v0 += a2.x; v1 += a2.y;
                }
                if (mode >= 1) {
                    v0 = (v0 >= 0.f) ? v0 : 0.01f * v0;
                    v1 = (v1 >= 0.f) ? v1 : 0.01f * v1;
                }
                if (cs.f16out)
                    cs.out16[(size_t)gr0 * 64 + kstep * 8 + slot] = packh2(v0, v1);
                else
                    *reinterpret_cast<float2*>(cs.outf + (size_t)gr0 * H + col) = make_float2(v0, v1);
            }
            if (gr1 < n) {
                float v2 = acc[mt][nt][2] * inv1;
                float v3 = acc[mt][nt][3] * inv1;
                if (mode == 2) {
                    float2 a2 = unpackh2(cs.addin16[(size_t)gr1 * 64 + kstep * 8 + slot]);
                    v2 += a2.x; v3 += a2.y;
                }
                if (mode >= 1) {
                    v2 = (v2 >= 0.f) ? v2 : 0.01f * v2;
                    v3 = (v3 >= 0.f) ? v3 : 0.01f * v3;
                }
                if (cs.f16out)
                    cs.out16[(size_t)gr1 * 64 + kstep * 8 + slot] = packh2(v2, v3);
                else
                    *reinterpret_cast<float2*>(cs.outf + (size_t)gr1 * H + col) = make_float2(v2, v3);
            }
        }
    }
}

// ---------------- host ----------------
extern "C" void kernel_launch(void* const* d_in, const int* in_sizes, int n_in,
                              void* d_out, int out_size)
{
    const float* x_ip  = (const float*)d_in[0];
    const float* x_con = (const float*)d_in[1];
    const int* src_ipcon = (const int*)d_in[2];
    const int* dst_ipcon = (const int*)d_in[3];
    const int* src_conip = (const int*)d_in[4];
    const int* dst_conip = (const int*)d_in[5];
    const int* src_ipip  = (const int*)d_in[6];
    const int* dst_ipip  = (const int*)d_in[7];
    const int* src_csrc  = (const int*)d_in[8];
    const int* dst_csrc  = (const int*)d_in[9];
    const int* src_cdst  = (const int*)d_in[10];
    const int* dst_cdst  = (const int*)d_in[11];
    const float* Wl_t = (const float*)d_in[12];
    const float* bl_t = (const float*)d_in[13];
    const float* Wr_t = (const float*)d_in[14];
    const float* Wl_s = (const float*)d_in[15];
    const float* bl_s = (const float*)d_in[16];
    const float* Wr_s = (const float*)d_in[17];

    const int n_ip  = in_sizes[0] / H;
    const int n_con = in_sizes[1] / H;
    const int nE_ipcon = in_sizes[2];
    const int nE_conip = in_sizes[4];
    const int nE_ipip  = in_sizes[6];
    const int nE_csrc  = in_sizes[8];
    const int nE_cdst  = in_sizes[10];

    uint32_t *s0, *s1, *s2, *wsp, *x16ip, *x16con, *ipA, *ipB, *conA, *conB, *tmpC;
    int *cnt, *off, *eidx, *part;
    cudaGetSymbolAddress((void**)&s0,     g_s0);
    cudaGetSymbolAddress((void**)&s1,     g_s1);
    cudaGetSymbolAddress((void**)&s2,     g_s2);
    cudaGetSymbolAddress((void**)&x16ip,  g_x16ip);
    cudaGetSymbolAddress((void**)&x16con, g_x16con);
    cudaGetSymbolAddress((void**)&ipA,    g_ipA);
    cudaGetSymbolAddress((void**)&ipB,    g_ipB);
    cudaGetSymbolAddress((void**)&conA,   g_conA);
    cudaGetSymbolAddress((void**)&conB,   g_conB);
    cudaGetSymbolAddress((void**)&tmpC,   g_tmpC);
    cudaGetSymbolAddress((void**)&wsp,    g_wsplit);
    cudaGetSymbolAddress((void**)&cnt,    g_cnt);
    cudaGetSymbolAddress((void**)&off,    g_off);
    cudaGetSymbolAddress((void**)&eidx,   g_eidx);
    cudaGetSymbolAddress((void**)&part,   g_part);

    cudaFuncSetAttribute(combine_fused_kernel, cudaFuncAttributeMaxDynamicSharedMemorySize, DSMEM_BYTES);

    float* out = (float*)d_out;

    BuildParams bp;
    bp.e[0] = { src_ipip,  dst_ipip,  nE_ipip,  n_ip,  0,                0 };
    bp.e[1] = { src_csrc,  dst_csrc,  nE_csrc,  n_con, n_ip,             nE_ipip };
    bp.e[2] = { src_cdst,  dst_cdst,  nE_cdst,  n_con, n_ip + n_con,     nE_ipip + nE_csrc };
    bp.e[3] = { src_ipcon, dst_ipcon, nE_ipcon, n_con, n_ip + 2 * n_con, nE_ipip + nE_csrc + nE_cdst };
    bp.e[4] = { src_conip, dst_conip, nE_conip, n_ip,  n_ip + 3 * n_con, nE_ipip + nE_csrc + nE_cdst + nE_ipcon };

    int maxE = nE_ipip;
    if (nE_csrc  > maxE) maxE = nE_csrc;
    if (nE_cdst  > maxE) maxE = nE_cdst;
    if (nE_ipcon > maxE) maxE = nE_ipcon;
    if (nE_conip > maxE) maxE = nE_conip;
    const int cntBlocks  = (maxE + 255) / 256;
    const int convIpB  = (n_ip * 2 + 255) / 256;
    const int convConB = (n_con * 2 + 255) / 256;

    precount_kernel<<<640 + 5 * cntBlocks + convIpB + convConB, 256>>>(
        Wl_t, Wr_t, Wl_s, Wr_s, wsp, bp, cnt, cntBlocks,
        x_ip, x_con, x16ip, x16con, n_ip, n_con, convIpB, convConB);
    scan_phase1<<<dim3(MAXB, 5), 1024>>>(bp, cnt, off, part);
    scan_phase23<<<dim3(MAXB, 5), 1024>>>(bp, off, part);
    fill_kernel<<<dim3(cntBlocks, 5), 256>>>(bp, cnt, off, eidx);

    const int* off0 = off + bp.e[0].dstbase + 0;
    const int* off1 = off + bp.e[1].dstbase + 1;
    const int* off2 = off + bp.e[2].dstbase + 2;
    const int* off3 = off + bp.e[3].dstbase + 3;
    const int* off4 = off + bp.e[4].dstbase + 4;
    const int* ei0 = eidx + bp.e[0].ebase;
    const int* ei1 = eidx + bp.e[1].ebase;
    const int* ei2 = eidx + bp.e[2].ebase;
    const int* ei3 = eidx + bp.e[3].ebase;
    const int* ei4 = eidx + bp.e[4].ebase;

    const int nbIP  = (n_ip  + 255) / 256;
    const int nbCON = (n_con + 255) / 256;
    // agg: 2 rows/warp -> warps = ceil(n/2), threads = warps*32
    const int aggBlocksCon = (((n_con + 1) / 2) * 32 + 255) / 256;
    const size_t WSZ = 16384;

    for (int l = 0; l < 2; l++) {
        const uint32_t* xi = (l == 0) ? x16ip  : ipB;
        const uint32_t* xc = (l == 0) ? x16con : conB;

        const float* b0 = bl_t + (size_t)(l * 3 + 0) * H;
        const float* b1 = bl_t + (size_t)(l * 3 + 1) * H;
        const float* b2 = bl_t + (size_t)(l * 3 + 2) * H;
        const float* bs0 = bl_s + (size_t)(l * 2 + 0) * H;
        const float* bs1 = bl_s + (size_t)(l * 2 + 1) * H;

        // ---------- temporal aggregation (3 segments, fused) ----------
        AggSeg a0 = { xi, off0, ei0, s0, n_ip };
        AggSeg a1 = { xc, off1, ei1, s1, n_con };
        AggSeg a2 = { xc, off2, ei2, s2, n_con };
        agg_fused_kernel<<<dim3(aggBlocksCon, 3), 256>>>(a0, a1, a2);

        // ---------- temporal combines ----------
        CombSeg cC1 = { s1, xc, wsp + (size_t)(l * 3 + 1) * WSZ, b1, nullptr, nullptr, tmpC, n_con, nbCON, 0, 1 };
        CombSeg cIP = { s0, xi, wsp + (size_t)(l * 3 + 0) * WSZ, b0, nullptr, nullptr, ipA,  n_ip,  nbIP,  1, 1 };
        combine_fused_kernel<<<nbCON + nbIP, 512, DSMEM_BYTES>>>(cC1, cIP);

        CombSeg cC2 = { s2, xc, wsp + (size_t)(l * 3 + 2) * WSZ, b2, tmpC, nullptr, conA, n_con, nbCON, 2, 1 };
        CombSeg cNil = {};
        combine_fused_kernel<<<nbCON, 512, DSMEM_BYTES>>>(cC2, cNil);

        // ---------- spatial aggregation (2 segments, fused) ----------
        AggSeg a3 = { ipA,  off3, ei3, s1, n_con };
        AggSeg a4 = { conA, off4, ei4, s0, n_ip };
        agg_fused_kernel<<<dim3(aggBlocksCon, 2), 256>>>(a3, a4, a4);

        // ---------- spatial combines fused ----------
        if (l == 0) {
            CombSeg cSC = { s1, conA, wsp + (size_t)(6 + 0) * WSZ, bs0, nullptr, nullptr, conB, n_con, nbCON, 1, 1 };
            CombSeg cSI = { s0, ipA,  wsp + (size_t)(6 + 1) * WSZ, bs1, nullptr, nullptr, ipB,  n_ip,  nbIP,  1, 1 };
            combine_fused_kernel<<<nbCON + nbIP, 512, DSMEM_BYTES>>>(cSC, cSI);
        } else {
            CombSeg cSC = { s1, conA, wsp + (size_t)(6 + 2) * WSZ, bs0, nullptr, out + (size_t)n_ip * H, nullptr, n_con, nbCON, 1, 0 };
            CombSeg cSI = { s0, ipA,  wsp + (size_t)(6 + 3) * WSZ, bs1, nullptr, out, nullptr, n_ip,  nbIP,  1, 0 };
            combine_fused_kernel<<<nbCON + nbIP, 512, DSMEM_BYTES>>>(cSC, cSI);
        }
    }
}